// round 3
// baseline (speedup 1.0000x reference)
#include <cuda_runtime.h>

// FrameAlignedGNNLayer3D: per-edge frame-aligned features -> 3-layer MLP (10->64->64->2)
// over S=4 slots -> segment-sum into H_new[i].
//
// Round 3: root cause of the 717 trap was edge_index dtype. The harness dtype
// contract has no int64 mapping -> edge_index is materialized as int32. Reading
// it as long long produced garbage gather indices -> generic-address trap.
// Now: default to int32 decode, with a deterministic device-side probe that
// detects a true int64 layout (all-high-words-zero across 16 samples) as
// insurance.

#define S_SLOTS 4
#define HID 64
#define IN_DIM 10

__device__ int g_edge_is_i64;   // 1 if buffer is little-endian int64 pairs

__device__ __forceinline__ float silu(float v) {
    return v / (1.0f + __expf(-v));
}

__global__ void detect_edge_dtype_kernel(const int* __restrict__ edge32, int n32) {
    // If the buffer holds int64 values (< 2^31), every odd int32 word is 0.
    // Sample 16 odd positions spread across the buffer; all-zero => int64.
    if (threadIdx.x == 0 && blockIdx.x == 0) {
        int any_nonzero = 0;
        for (int s = 0; s < 16; s++) {
            long long pos = 1 + (long long)s * ((n32 - 2) / 16);
            pos |= 1;  // force odd
            if (pos < n32) any_nonzero |= (edge32[pos] != 0);
        }
        g_edge_is_i64 = any_nonzero ? 0 : 1;
    }
}

__global__ void zero_out_kernel(float* __restrict__ out, int n) {
    int idx = blockIdx.x * blockDim.x + threadIdx.x;
    if (idx < n) out[idx] = 0.0f;
}

__global__ __launch_bounds__(256, 2)
void gnn_edge_mlp_kernel(
    const float* __restrict__ x,        // (N,3)
    const float* __restrict__ theta,    // (N,)
    const float* __restrict__ H,        // (N,S,2)
    const int*   __restrict__ edge,     // (2,E) int32 (or int64, see flag)
    const float* __restrict__ W1,       // (10,64)
    const float* __restrict__ b1,       // (64,)
    const float* __restrict__ W2,       // (64,64)
    const float* __restrict__ b2,       // (64,)
    const float* __restrict__ W3,       // (64,2)
    const float* __restrict__ b3,       // (2,)
    float* __restrict__ out,            // (N,S,2)
    int nE)
{
    __shared__ __align__(16) float sW1[IN_DIM * HID];   // [d][k]
    __shared__ __align__(16) float sB1[HID];
    __shared__ __align__(16) float sW2[HID * HID];      // [k][j]
    __shared__ __align__(16) float sB2[HID];
    __shared__ __align__(16) float sW3c0[HID];          // W3[:,0]
    __shared__ __align__(16) float sW3c1[HID];          // W3[:,1]
    __shared__ float sB3[2];

    const int t = threadIdx.x;
    for (int idx = t; idx < IN_DIM * HID; idx += 256) sW1[idx] = W1[idx];
    for (int idx = t; idx < HID * HID;   idx += 256) sW2[idx] = W2[idx];
    if (t < HID) {
        sB1[t]   = b1[t];
        sB2[t]   = b2[t];
        sW3c0[t] = W3[2 * t + 0];
        sW3c1[t] = W3[2 * t + 1];
    }
    if (t < 2) sB3[t] = b3[t];
    __syncthreads();

    const long long item = (long long)blockIdx.x * blockDim.x + t;
    const long long n_items = (long long)nE * S_SLOTS;
    if (item >= n_items) return;

    const int e = (int)(item >> 2);
    const int s = (int)(item & 3);

    int i, j;
    if (g_edge_is_i64) {   // uniform branch, same for all threads
        const long long* e64 = (const long long*)edge;
        i = (int)e64[e];
        j = (int)e64[(long long)nE + e];
    } else {
        i = edge[e];
        j = edge[nE + e];
    }

    // ---- geometric features ----
    const float dx0 = x[3 * j + 0] - x[3 * i + 0];
    const float dx1 = x[3 * j + 1] - x[3 * i + 1];
    const float dx2 = x[3 * j + 2] - x[3 * i + 2];

    const float rxy2 = dx0 * dx0 + dx1 * dx1;
    const float r3d  = sqrtf(rxy2 + dx2 * dx2);
    const float rxy  = sqrtf(rxy2);

    const float ti  = theta[i];
    const float tj  = theta[j];
    const float phi = atan2f(dx1, dx0);
    const float dphi = phi - ti;
    const float dth  = tj - ti;

    float s2, c2;
    sincosf(2.0f * dth, &s2, &c2);
    float sp, cp;
    sincosf(dphi, &sp, &cp);

    const float sgn = (dx2 > 0.0f) ? 1.0f : ((dx2 < 0.0f) ? -1.0f : 0.0f);

    // ---- slot input (rotated H_j + geom) ----
    const float vx = H[((long long)j * S_SLOTS + s) * 2 + 0];
    const float vy = H[((long long)j * S_SLOTS + s) * 2 + 1];

    float in[IN_DIM];
    in[0] = c2 * vx - s2 * vy;
    in[1] = s2 * vx + c2 * vy;
    in[2] = r3d;
    in[3] = rxy;
    in[4] = dx2;
    in[5] = sp;
    in[6] = cp;
    in[7] = s2;
    in[8] = c2;
    in[9] = sgn * s2;

    // ---- layer 1: h1 = silu(in @ W1 + b1), fully unrolled ----
    float h1[HID];
    #pragma unroll
    for (int k = 0; k < HID; k += 4) {
        float4 acc = *reinterpret_cast<const float4*>(sB1 + k);
        #pragma unroll
        for (int d = 0; d < IN_DIM; d++) {
            const float4 w = *reinterpret_cast<const float4*>(sW1 + d * HID + k);
            acc.x = fmaf(in[d], w.x, acc.x);
            acc.y = fmaf(in[d], w.y, acc.y);
            acc.z = fmaf(in[d], w.z, acc.z);
            acc.w = fmaf(in[d], w.w, acc.w);
        }
        h1[k + 0] = silu(acc.x);
        h1[k + 1] = silu(acc.y);
        h1[k + 2] = silu(acc.z);
        h1[k + 3] = silu(acc.w);
    }

    // ---- layers 2+3 fused: never materialize h2 ----
    float o0 = sB3[0];
    float o1 = sB3[1];
    for (int jj = 0; jj < HID; jj += 4) {   // NOT unrolled: keeps I$ footprint small
        float4 acc = *reinterpret_cast<const float4*>(sB2 + jj);
        #pragma unroll
        for (int k = 0; k < HID; k++) {     // h1[k] stays in registers -> full unroll
            const float4 w = *reinterpret_cast<const float4*>(sW2 + k * HID + jj);
            acc.x = fmaf(h1[k], w.x, acc.x);
            acc.y = fmaf(h1[k], w.y, acc.y);
            acc.z = fmaf(h1[k], w.z, acc.z);
            acc.w = fmaf(h1[k], w.w, acc.w);
        }
        acc.x = silu(acc.x);
        acc.y = silu(acc.y);
        acc.z = silu(acc.z);
        acc.w = silu(acc.w);

        const float4 w0 = *reinterpret_cast<const float4*>(sW3c0 + jj);
        const float4 w1 = *reinterpret_cast<const float4*>(sW3c1 + jj);
        o0 = fmaf(acc.x, w0.x, o0); o0 = fmaf(acc.y, w0.y, o0);
        o0 = fmaf(acc.z, w0.z, o0); o0 = fmaf(acc.w, w0.w, o0);
        o1 = fmaf(acc.x, w1.x, o1); o1 = fmaf(acc.y, w1.y, o1);
        o1 = fmaf(acc.z, w1.z, o1); o1 = fmaf(acc.w, w1.w, o1);
    }

    // ---- scatter-add into H_new[i][s] ----
    float* o = out + ((long long)i * S_SLOTS + s) * 2;
    atomicAdd(o + 0, o0);
    atomicAdd(o + 1, o1);
}

extern "C" void kernel_launch(void* const* d_in, const int* in_sizes, int n_in,
                              void* d_out, int out_size) {
    const float* x     = (const float*)d_in[0];
    const float* theta = (const float*)d_in[1];
    const float* H     = (const float*)d_in[2];
    const int*   edge  = (const int*)d_in[3];
    const float* W1    = (const float*)d_in[4];
    const float* b1    = (const float*)d_in[5];
    const float* W2    = (const float*)d_in[6];
    const float* b2    = (const float*)d_in[7];
    const float* W3    = (const float*)d_in[8];
    const float* b3    = (const float*)d_in[9];

    const int nE = in_sizes[3] / 2;   // edge_index has 2*E entries

    detect_edge_dtype_kernel<<<1, 32>>>(edge, in_sizes[3]);
    zero_out_kernel<<<(out_size + 255) / 256, 256>>>((float*)d_out, out_size);

    const long long items = (long long)nE * S_SLOTS;
    const int blocks = (int)((items + 255) / 256);
    gnn_edge_mlp_kernel<<<blocks, 256>>>(x, theta, H, edge,
                                         W1, b1, W2, b2, W3, b3,
                                         (float*)d_out, nE);
}

// round 5
// speedup vs baseline: 2.5050x; 2.5050x over previous
#include <cuda_runtime.h>
#include <cuda_bf16.h>
#include <cstdint>

// FrameAlignedGNNLayer3D via mma.sync (sm_100-safe HMMA path; tcgen05 is
// locked out because the harness compiles for plain sm_100).
//
// Per 128-row tile (block = 256 threads, 8 warps, M=16 rows/warp):
//   SIMT features -> X smem (bf16 hi/lo, K padded 10->16)
//   L1: mma.sync m16n8k16, 3-term bf16 split, N=64  (A via ldmatrix)
//   silu + split IN REGISTERS (C-frag == next A-frag layout, no smem round trip)
//   L2: mma.sync, K=64, N=64, 3-term split (B via ldmatrix)
//   silu + 64->2 layer-3 + quad shuffle reduce + atomic scatter.

#define S_SLOTS 4
#define TILE 128
#define NTHREADS 256

// ---- smem layout (static, ~38KB) ----
#define XPITCH 48      // 16 bf16 (32B) + 16B pad -> conflict-free ldmatrix
#define WPITCH1 48
#define WPITCH2 144    // 64 bf16 (128B) + 16B pad
#define OFF_XHI  0
#define OFF_XLO  (OFF_XHI + 128 * XPITCH)      // 6144
#define OFF_W1H  (OFF_XLO + 128 * XPITCH)      // 12288
#define OFF_W1L  (OFF_W1H + 64 * WPITCH1)      // 15360
#define OFF_W2H  (OFF_W1L + 64 * WPITCH1)      // 18432
#define OFF_W2L  (OFF_W2H + 64 * WPITCH2)      // 27648
#define OFF_B1   (OFF_W2L + 64 * WPITCH2)      // 36864
#define OFF_B2   (OFF_B1 + 256)
#define OFF_W3   (OFF_B2 + 256)                // 64 float2 pairs
#define OFF_B3   (OFF_W3 + 512)
#define SMEM_BYTES (OFF_B3 + 16)

__device__ int g_edge_is_i64;

__global__ void detect_edge_dtype_kernel(const int* __restrict__ edge32, int n32) {
    if (threadIdx.x == 0 && blockIdx.x == 0) {
        int any_nonzero = 0;
        for (int s = 0; s < 16; s++) {
            long long pos = 1 + (long long)s * ((n32 - 2) / 16);
            pos |= 1;
            if (pos < n32) any_nonzero |= (edge32[pos] != 0);
        }
        g_edge_is_i64 = any_nonzero ? 0 : 1;
    }
}

__global__ void zero_out_kernel(float* __restrict__ out, int n) {
    int idx = blockIdx.x * blockDim.x + threadIdx.x;
    if (idx < n) out[idx] = 0.0f;
}

__device__ __forceinline__ float silu(float v) {
    return __fdividef(v, 1.0f + __expf(-v));
}

__device__ __forceinline__ uint32_t smem_u32(const void* p) {
    uint32_t a;
    asm("{ .reg .u64 t; cvta.to.shared.u64 t, %1; cvt.u32.u64 %0, t; }" : "=r"(a) : "l"(p));
    return a;
}

__device__ __forceinline__ void ldm4(uint32_t addr, uint32_t& r0, uint32_t& r1,
                                     uint32_t& r2, uint32_t& r3) {
    asm volatile("ldmatrix.sync.aligned.m8n8.x4.shared.b16 {%0,%1,%2,%3}, [%4];"
                 : "=r"(r0), "=r"(r1), "=r"(r2), "=r"(r3) : "r"(addr));
}

__device__ __forceinline__ void mma16816(float* c, uint32_t a0, uint32_t a1,
                                         uint32_t a2, uint32_t a3,
                                         uint32_t b0, uint32_t b1) {
    asm volatile(
        "mma.sync.aligned.m16n8k16.row.col.f32.bf16.bf16.f32 "
        "{%0,%1,%2,%3}, {%4,%5,%6,%7}, {%8,%9}, {%0,%1,%2,%3};"
        : "+f"(c[0]), "+f"(c[1]), "+f"(c[2]), "+f"(c[3])
        : "r"(a0), "r"(a1), "r"(a2), "r"(a3), "r"(b0), "r"(b1));
}

__device__ __forceinline__ uint32_t pack_bf2(float v0, float v1) {
    __nv_bfloat162 p = __floats2bfloat162_rn(v0, v1);   // .x = v0 (low half)
    return *reinterpret_cast<uint32_t*>(&p);
}

__global__ __launch_bounds__(NTHREADS)
void gnn_mma_kernel(
    const float* __restrict__ x, const float* __restrict__ theta,
    const float* __restrict__ H, const int* __restrict__ edge,
    const float* __restrict__ W1, const float* __restrict__ b1,
    const float* __restrict__ W2, const float* __restrict__ b2,
    const float* __restrict__ W3, const float* __restrict__ b3,
    float* __restrict__ out, int nE)
{
    __shared__ __align__(16) char smem[SMEM_BYTES];
    const uint32_t sb = smem_u32(smem);

    const int t    = threadIdx.x;
    const int lane = t & 31;
    const int w    = t >> 5;           // warp id, rows [16w, 16w+16)
    const int is64 = g_edge_is_i64;
    const long long items = (long long)nE * S_SLOTS;

    // ================= stage weights =================
    // W1s[n][kk] = W1[kk][n], split hi/lo, pitch 48B; pad kk=10..15 with zeros.
    for (int idx = t; idx < 64 * 10; idx += NTHREADS) {
        int kk = idx / 64, n = idx % 64;
        float v = W1[kk * 64 + n];
        __nv_bfloat16 hi = __float2bfloat16_rn(v);
        __nv_bfloat16 lo = __float2bfloat16_rn(v - __bfloat162float(hi));
        *(__nv_bfloat16*)(smem + OFF_W1H + n * WPITCH1 + kk * 2) = hi;
        *(__nv_bfloat16*)(smem + OFF_W1L + n * WPITCH1 + kk * 2) = lo;
    }
    if (t < 64) {  // zero pad kk 10..15 of W1
        for (int kk = 10; kk < 16; kk++) {
            *(__nv_bfloat16*)(smem + OFF_W1H + t * WPITCH1 + kk * 2) = __float2bfloat16_rn(0.f);
            *(__nv_bfloat16*)(smem + OFF_W1L + t * WPITCH1 + kk * 2) = __float2bfloat16_rn(0.f);
        }
    }
    // W2s[n][k] = W2[k][n], pitch 144B
    for (int idx = t; idx < 64 * 64; idx += NTHREADS) {
        int k = idx >> 6, n = idx & 63;
        float v = W2[k * 64 + n];
        __nv_bfloat16 hi = __float2bfloat16_rn(v);
        __nv_bfloat16 lo = __float2bfloat16_rn(v - __bfloat162float(hi));
        *(__nv_bfloat16*)(smem + OFF_W2H + n * WPITCH2 + k * 2) = hi;
        *(__nv_bfloat16*)(smem + OFF_W2L + n * WPITCH2 + k * 2) = lo;
    }
    if (t < 64) {
        ((float*)(smem + OFF_B1))[t] = b1[t];
        ((float*)(smem + OFF_B2))[t] = b2[t];
        ((float2*)(smem + OFF_W3))[t] = make_float2(W3[2 * t], W3[2 * t + 1]);
    }
    if (t < 2) ((float*)(smem + OFF_B3))[t] = b3[t];

    // ================= features for this tile (rows 0..127) =================
    if (t < TILE) {
        const long long item = (long long)blockIdx.x * TILE + t;
        float f[10] = {0, 0, 0, 0, 0, 0, 0, 0, 0, 0};
        if (item < items) {
            const int e = (int)(item >> 2);
            const int s = (int)(item & 3);
            int i_node, j_node;
            if (is64) {
                const long long* e64 = (const long long*)edge;
                i_node = (int)e64[e]; j_node = (int)e64[(long long)nE + e];
            } else {
                i_node = edge[e]; j_node = edge[nE + e];
            }
            const float dx0 = x[3 * j_node + 0] - x[3 * i_node + 0];
            const float dx1 = x[3 * j_node + 1] - x[3 * i_node + 1];
            const float dx2 = x[3 * j_node + 2] - x[3 * i_node + 2];
            const float rxy2 = dx0 * dx0 + dx1 * dx1;
            const float ti = theta[i_node], tj = theta[j_node];
            float s2, c2; sincosf(2.0f * (tj - ti), &s2, &c2);
            float sp, cp; sincosf(atan2f(dx1, dx0) - ti, &sp, &cp);
            const float sgn = (dx2 > 0.0f) ? 1.0f : ((dx2 < 0.0f) ? -1.0f : 0.0f);
            const float vx = H[((long long)j_node * S_SLOTS + s) * 2 + 0];
            const float vy = H[((long long)j_node * S_SLOTS + s) * 2 + 1];
            f[0] = c2 * vx - s2 * vy;  f[1] = s2 * vx + c2 * vy;
            f[2] = sqrtf(rxy2 + dx2 * dx2);  f[3] = sqrtf(rxy2);  f[4] = dx2;
            f[5] = sp;  f[6] = cp;  f[7] = s2;  f[8] = c2;  f[9] = sgn * s2;
        }
        char* xh = smem + OFF_XHI + t * XPITCH;
        char* xl = smem + OFF_XLO + t * XPITCH;
        #pragma unroll
        for (int c = 0; c < 10; c += 2) {
            __nv_bfloat16 h0 = __float2bfloat16_rn(f[c]);
            __nv_bfloat16 h1 = __float2bfloat16_rn(f[c + 1]);
            float r0 = f[c] - __bfloat162float(h0);
            float r1 = f[c + 1] - __bfloat162float(h1);
            *(uint32_t*)(xh + c * 2) = pack_bf2(f[c] * 0.f + __bfloat162float(h0),
                                                __bfloat162float(h1));
            *(uint32_t*)(xl + c * 2) = pack_bf2(r0, r1);
        }
        *(uint32_t*)(xh + 20) = 0u; *(uint32_t*)(xh + 24) = 0u; *(uint32_t*)(xh + 28) = 0u;
        *(uint32_t*)(xl + 20) = 0u; *(uint32_t*)(xl + 24) = 0u; *(uint32_t*)(xl + 28) = 0u;
    }
    __syncthreads();

    // ================= ldmatrix address precompute =================
    const int sel = lane >> 3;       // 0..3
    const int r8  = lane & 7;        // 0..7
    // A (X) tiles: m0 rows g k0 | m1 rows g+8 k0 | m2 rows g k8 | m3 rows g+8 k8
    const uint32_t a_off = (uint32_t)((w * 16 + r8 + (sel & 1) * 8) * XPITCH + (sel >> 1) * 16);
    // W tiles: m0 n-rows(j) kLo | m1 n-rows(j) kHi | m2 n-rows(j+1) kLo | m3 kHi
    const uint32_t w1_off = (uint32_t)(((sel >> 1) * 8 + r8) * WPITCH1 + (sel & 1) * 16);
    const uint32_t w2_off = (uint32_t)(((sel >> 1) * 8 + r8) * WPITCH2 + (sel & 1) * 16);

    // ================= layer 1: X(128x16) @ W1(16x64) =================
    uint32_t a1h[4], a1l[4];
    ldm4(sb + OFF_XHI + a_off, a1h[0], a1h[1], a1h[2], a1h[3]);
    ldm4(sb + OFF_XLO + a_off, a1l[0], a1l[1], a1l[2], a1l[3]);

    float c1[32];
    #pragma unroll
    for (int i = 0; i < 32; i++) c1[i] = 0.0f;

    #pragma unroll
    for (int jp = 0; jp < 8; jp += 2) {
        uint32_t wh0, wh1, wh2, wh3, wl0, wl1, wl2, wl3;
        ldm4(sb + OFF_W1H + jp * 8 * WPITCH1 + w1_off, wh0, wh1, wh2, wh3);
        ldm4(sb + OFF_W1L + jp * 8 * WPITCH1 + w1_off, wl0, wl1, wl2, wl3);
        mma16816(c1 + 4 * jp,     a1h[0], a1h[1], a1h[2], a1h[3], wh0, wh1);
        mma16816(c1 + 4 * jp,     a1l[0], a1l[1], a1l[2], a1l[3], wh0, wh1);
        mma16816(c1 + 4 * jp,     a1h[0], a1h[1], a1h[2], a1h[3], wl0, wl1);
        mma16816(c1 + 4 * jp + 4, a1h[0], a1h[1], a1h[2], a1h[3], wh2, wh3);
        mma16816(c1 + 4 * jp + 4, a1l[0], a1l[1], a1l[2], a1l[3], wh2, wh3);
        mma16816(c1 + 4 * jp + 4, a1h[0], a1h[1], a1h[2], a1h[3], wl2, wl3);
    }

    // ============ epilogue 1 (registers only): bias + silu + split ============
    // C frag of n-tile j: (d0,d1)=row g cols 8j+2t,+1 ; (d2,d3)=row g+8.
    // These are exactly layer-2 A-frag elements: n-tile 2q -> a0,a1 ; 2q+1 -> a2,a3.
    const int cb = 2 * (lane & 3);   // 2t
    uint32_t a2h[16], a2l[16];
    #pragma unroll
    for (int j = 0; j < 8; j++) {
        const float2 bia = *(const float2*)(smem + OFF_B1 + (8 * j + cb) * 4);
        float v0 = silu(c1[4 * j + 0] + bia.x);
        float v1 = silu(c1[4 * j + 1] + bia.y);
        float v2 = silu(c1[4 * j + 2] + bia.x);
        float v3 = silu(c1[4 * j + 3] + bia.y);
        __nv_bfloat16 h0 = __float2bfloat16_rn(v0), h1 = __float2bfloat16_rn(v1);
        __nv_bfloat16 h2 = __float2bfloat16_rn(v2), h3 = __float2bfloat16_rn(v3);
        const int q = j >> 1, hi2 = (j & 1) * 2;    // a-frag reg index base
        a2h[4 * q + hi2 + 0] = pack_bf2(__bfloat162float(h0), __bfloat162float(h1));
        a2h[4 * q + hi2 + 1] = pack_bf2(__bfloat162float(h2), __bfloat162float(h3));
        a2l[4 * q + hi2 + 0] = pack_bf2(v0 - __bfloat162float(h0), v1 - __bfloat162float(h1));
        a2l[4 * q + hi2 + 1] = pack_bf2(v2 - __bfloat162float(h2), v3 - __bfloat162float(h3));
    }

    // ================= layer 2: H1(128x64) @ W2(64x64) =================
    float c2[32];
    #pragma unroll
    for (int i = 0; i < 32; i++) c2[i] = 0.0f;

    #pragma unroll
    for (int q = 0; q < 4; q++) {
        #pragma unroll
        for (int jp = 0; jp < 8; jp += 2) {
            uint32_t wh0, wh1, wh2, wh3, wl0, wl1, wl2, wl3;
            ldm4(sb + OFF_W2H + jp * 8 * WPITCH2 + q * 32 + w2_off, wh0, wh1, wh2, wh3);
            ldm4(sb + OFF_W2L + jp * 8 * WPITCH2 + q * 32 + w2_off, wl0, wl1, wl2, wl3);
            mma16816(c2 + 4 * jp,     a2h[4*q+0], a2h[4*q+1], a2h[4*q+2], a2h[4*q+3], wh0, wh1);
            mma16816(c2 + 4 * jp,     a2l[4*q+0], a2l[4*q+1], a2l[4*q+2], a2l[4*q+3], wh0, wh1);
            mma16816(c2 + 4 * jp,     a2h[4*q+0], a2h[4*q+1], a2h[4*q+2], a2h[4*q+3], wl0, wl1);
            mma16816(c2 + 4 * jp + 4, a2h[4*q+0], a2h[4*q+1], a2h[4*q+2], a2h[4*q+3], wh2, wh3);
            mma16816(c2 + 4 * jp + 4, a2l[4*q+0], a2l[4*q+1], a2l[4*q+2], a2l[4*q+3], wh2, wh3);
            mma16816(c2 + 4 * jp + 4, a2h[4*q+0], a2h[4*q+1], a2h[4*q+2], a2h[4*q+3], wl2, wl3);
        }
    }

    // ============ epilogue 2: bias + silu + layer3 + reduce + scatter ============
    float o0a = 0.f, o1a = 0.f, o0b = 0.f, o1b = 0.f;
    #pragma unroll
    for (int j = 0; j < 8; j++) {
        const int c0 = 8 * j + cb;
        const float2 bia = *(const float2*)(smem + OFF_B2 + c0 * 4);
        const float2 w3a = *(const float2*)(smem + OFF_W3 + c0 * 8);
        const float2 w3b = *(const float2*)(smem + OFF_W3 + (c0 + 1) * 8);
        float v0 = silu(c2[4 * j + 0] + bia.x);
        float v1 = silu(c2[4 * j + 1] + bia.y);
        float v2 = silu(c2[4 * j + 2] + bia.x);
        float v3 = silu(c2[4 * j + 3] + bia.y);
        o0a = fmaf(v0, w3a.x, fmaf(v1, w3b.x, o0a));
        o1a = fmaf(v0, w3a.y, fmaf(v1, w3b.y, o1a));
        o0b = fmaf(v2, w3a.x, fmaf(v3, w3b.x, o0b));
        o1b = fmaf(v2, w3a.y, fmaf(v3, w3b.y, o1b));
    }
    // quad reduce (lanes 4g..4g+3 share rows g, g+8)
    #pragma unroll
    for (int m = 1; m <= 2; m <<= 1) {
        o0a += __shfl_xor_sync(0xffffffffu, o0a, m);
        o1a += __shfl_xor_sync(0xffffffffu, o1a, m);
        o0b += __shfl_xor_sync(0xffffffffu, o0b, m);
        o1b += __shfl_xor_sync(0xffffffffu, o1b, m);
    }
    if ((lane & 3) == 0) {
        const float bb0 = ((float*)(smem + OFF_B3))[0];
        const float bb1 = ((float*)(smem + OFF_B3))[1];
        const int g = lane >> 2;
        #pragma unroll
        for (int half = 0; half < 2; half++) {
            const long long item = (long long)blockIdx.x * TILE + w * 16 + g + 8 * half;
            if (item < items) {
                const int e = (int)(item >> 2);
                const int s = (int)(item & 3);
                int i_node;
                if (is64) i_node = (int)((const long long*)edge)[e];
                else      i_node = edge[e];
                float* o = out + ((long long)i_node * S_SLOTS + s) * 2;
                atomicAdd(o + 0, (half ? o0b : o0a) + bb0);
                atomicAdd(o + 1, (half ? o1b : o1a) + bb1);
            }
        }
    }
}

extern "C" void kernel_launch(void* const* d_in, const int* in_sizes, int n_in,
                              void* d_out, int out_size) {
    const float* x     = (const float*)d_in[0];
    const float* theta = (const float*)d_in[1];
    const float* H     = (const float*)d_in[2];
    const int*   edge  = (const int*)d_in[3];
    const float* W1    = (const float*)d_in[4];
    const float* b1    = (const float*)d_in[5];
    const float* W2    = (const float*)d_in[6];
    const float* b2    = (const float*)d_in[7];
    const float* W3    = (const float*)d_in[8];
    const float* b3    = (const float*)d_in[9];

    const int nE = in_sizes[3] / 2;

    detect_edge_dtype_kernel<<<1, 32>>>(edge, in_sizes[3]);
    zero_out_kernel<<<(out_size + 255) / 256, 256>>>((float*)d_out, out_size);

    const long long items = (long long)nE * S_SLOTS;
    const int ntiles = (int)((items + TILE - 1) / TILE);
    gnn_mma_kernel<<<ntiles, NTHREADS>>>(x, theta, H, edge,
                                         W1, b1, W2, b2, W3, b3,
                                         (float*)d_out, nE);
}

// round 6
// speedup vs baseline: 2.6251x; 1.0479x over previous
#include <cuda_runtime.h>
#include <cuda_bf16.h>
#include <cstdint>

// FrameAlignedGNNLayer3D via mma.sync (sm_100-safe HMMA path).
// R6: (1) 2 CTAs/SM via __launch_bounds__(256,2) + register-slim layer-2
//     (epilogue-1 fused into the q-loop: a2 frags are 8 regs, not 32);
//     (2) per-edge geometry computed once (warp 0) instead of 4x per slot.

#define S_SLOTS 4
#define TILE 128
#define NTHREADS 256

// ---- smem layout (static, <40KB) ----
#define XPITCH 48      // 16 bf16 (32B) + 16B pad -> conflict-free ldmatrix
#define WPITCH1 48
#define WPITCH2 144    // 64 bf16 (128B) + 16B pad
#define GPITCH 12      // floats per edge-geometry record
#define OFF_XHI  0
#define OFF_XLO  (OFF_XHI + 128 * XPITCH)      // 6144
#define OFF_W1H  (OFF_XLO + 128 * XPITCH)      // 12288
#define OFF_W1L  (OFF_W1H + 64 * WPITCH1)      // 15360
#define OFF_W2H  (OFF_W1L + 64 * WPITCH1)      // 18432
#define OFF_W2L  (OFF_W2H + 64 * WPITCH2)      // 27648
#define OFF_B1   (OFF_W2L + 64 * WPITCH2)      // 36864
#define OFF_B2   (OFF_B1 + 256)
#define OFF_W3   (OFF_B2 + 256)                // 64 float2 pairs
#define OFF_B3   (OFF_W3 + 512)
#define OFF_GEOM (OFF_B3 + 16)                 // 32 edges x 12 floats
#define SMEM_BYTES (OFF_GEOM + 32 * GPITCH * 4)

__device__ int g_edge_is_i64;

__global__ void detect_edge_dtype_kernel(const int* __restrict__ edge32, int n32) {
    if (threadIdx.x == 0 && blockIdx.x == 0) {
        int any_nonzero = 0;
        for (int s = 0; s < 16; s++) {
            long long pos = 1 + (long long)s * ((n32 - 2) / 16);
            pos |= 1;
            if (pos < n32) any_nonzero |= (edge32[pos] != 0);
        }
        g_edge_is_i64 = any_nonzero ? 0 : 1;
    }
}

__global__ void zero_out_kernel(float* __restrict__ out, int n) {
    int idx = blockIdx.x * blockDim.x + threadIdx.x;
    if (idx < n) out[idx] = 0.0f;
}

__device__ __forceinline__ float silu(float v) {
    return __fdividef(v, 1.0f + __expf(-v));
}

__device__ __forceinline__ uint32_t smem_u32(const void* p) {
    uint32_t a;
    asm("{ .reg .u64 t; cvta.to.shared.u64 t, %1; cvt.u32.u64 %0, t; }" : "=r"(a) : "l"(p));
    return a;
}

__device__ __forceinline__ void ldm4(uint32_t addr, uint32_t& r0, uint32_t& r1,
                                     uint32_t& r2, uint32_t& r3) {
    asm volatile("ldmatrix.sync.aligned.m8n8.x4.shared.b16 {%0,%1,%2,%3}, [%4];"
                 : "=r"(r0), "=r"(r1), "=r"(r2), "=r"(r3) : "r"(addr));
}

__device__ __forceinline__ void mma16816(float* c, uint32_t a0, uint32_t a1,
                                         uint32_t a2, uint32_t a3,
                                         uint32_t b0, uint32_t b1) {
    asm volatile(
        "mma.sync.aligned.m16n8k16.row.col.f32.bf16.bf16.f32 "
        "{%0,%1,%2,%3}, {%4,%5,%6,%7}, {%8,%9}, {%0,%1,%2,%3};"
        : "+f"(c[0]), "+f"(c[1]), "+f"(c[2]), "+f"(c[3])
        : "r"(a0), "r"(a1), "r"(a2), "r"(a3), "r"(b0), "r"(b1));
}

__device__ __forceinline__ uint32_t pack_bf2(float v0, float v1) {
    __nv_bfloat162 p = __floats2bfloat162_rn(v0, v1);   // .x = v0 (low half)
    return *reinterpret_cast<uint32_t*>(&p);
}

__global__ __launch_bounds__(NTHREADS, 2)
void gnn_mma_kernel(
    const float* __restrict__ x, const float* __restrict__ theta,
    const float* __restrict__ H, const int* __restrict__ edge,
    const float* __restrict__ W1, const float* __restrict__ b1,
    const float* __restrict__ W2, const float* __restrict__ b2,
    const float* __restrict__ W3, const float* __restrict__ b3,
    float* __restrict__ out, int nE)
{
    __shared__ __align__(16) char smem[SMEM_BYTES];
    const uint32_t sb = smem_u32(smem);

    const int t    = threadIdx.x;
    const int lane = t & 31;
    const int w    = t >> 5;           // warp id, rows [16w, 16w+16)
    const int is64 = g_edge_is_i64;
    const long long items = (long long)nE * S_SLOTS;

    // ================= stage weights =================
    for (int idx = t; idx < 64 * 10; idx += NTHREADS) {
        int kk = idx / 64, n = idx % 64;
        float v = W1[kk * 64 + n];
        __nv_bfloat16 hi = __float2bfloat16_rn(v);
        __nv_bfloat16 lo = __float2bfloat16_rn(v - __bfloat162float(hi));
        *(__nv_bfloat16*)(smem + OFF_W1H + n * WPITCH1 + kk * 2) = hi;
        *(__nv_bfloat16*)(smem + OFF_W1L + n * WPITCH1 + kk * 2) = lo;
    }
    if (t < 64) {  // zero pad kk 10..15 of W1
        for (int kk = 10; kk < 16; kk++) {
            *(__nv_bfloat16*)(smem + OFF_W1H + t * WPITCH1 + kk * 2) = __float2bfloat16_rn(0.f);
            *(__nv_bfloat16*)(smem + OFF_W1L + t * WPITCH1 + kk * 2) = __float2bfloat16_rn(0.f);
        }
    }
    for (int idx = t; idx < 64 * 64; idx += NTHREADS) {
        int k = idx >> 6, n = idx & 63;
        float v = W2[k * 64 + n];
        __nv_bfloat16 hi = __float2bfloat16_rn(v);
        __nv_bfloat16 lo = __float2bfloat16_rn(v - __bfloat162float(hi));
        *(__nv_bfloat16*)(smem + OFF_W2H + n * WPITCH2 + k * 2) = hi;
        *(__nv_bfloat16*)(smem + OFF_W2L + n * WPITCH2 + k * 2) = lo;
    }
    if (t < 64) {
        ((float*)(smem + OFF_B1))[t] = b1[t];
        ((float*)(smem + OFF_B2))[t] = b2[t];
        ((float2*)(smem + OFF_W3))[t] = make_float2(W3[2 * t], W3[2 * t + 1]);
    }
    if (t < 2) ((float*)(smem + OFF_B3))[t] = b3[t];

    // ================= per-edge geometry (warp 0, 32 edges/tile) =============
    if (t < 32) {
        const long long e = (long long)blockIdx.x * 32 + t;
        float g0 = 0.f, g1 = 0.f, g2 = 0.f, g3 = 0.f,
              g4 = 0.f, g5 = 0.f, g6 = 0.f, g7 = 0.f;
        int j_node = 0;
        if (e < nE) {
            int i_node;
            if (is64) {
                const long long* e64 = (const long long*)edge;
                i_node = (int)e64[e]; j_node = (int)e64[(long long)nE + e];
            } else {
                i_node = edge[e]; j_node = edge[nE + e];
            }
            const float dx0 = x[3 * j_node + 0] - x[3 * i_node + 0];
            const float dx1 = x[3 * j_node + 1] - x[3 * i_node + 1];
            const float dx2 = x[3 * j_node + 2] - x[3 * i_node + 2];
            const float rxy2 = dx0 * dx0 + dx1 * dx1;
            const float ti = theta[i_node], tj = theta[j_node];
            float s2, c2; sincosf(2.0f * (tj - ti), &s2, &c2);
            float sp, cp; sincosf(atan2f(dx1, dx0) - ti, &sp, &cp);
            const float sgn = (dx2 > 0.0f) ? 1.0f : ((dx2 < 0.0f) ? -1.0f : 0.0f);
            g0 = sqrtf(rxy2 + dx2 * dx2);  // r3d
            g1 = sqrtf(rxy2);              // rxy
            g2 = dx2;
            g3 = sp;  g4 = cp;
            g5 = s2;  g6 = c2;
            g7 = sgn * s2;
        }
        float* gp = (float*)(smem + OFF_GEOM) + t * GPITCH;
        gp[0] = g0; gp[1] = g1; gp[2] = g2; gp[3] = g3;
        gp[4] = g4; gp[5] = g5; gp[6] = g6; gp[7] = g7;
        ((int*)gp)[8] = j_node;
    }
    __syncthreads();

    // ================= per-row features (t < 128) =================
    if (t < TILE) {
        const int e_loc = t >> 2;
        const int s     = t & 3;
        const float* gp = (const float*)(smem + OFF_GEOM) + e_loc * GPITCH;
        const float s2 = gp[5], c2 = gp[6];
        const int j_node = ((const int*)gp)[8];
        const float2 hv = *(const float2*)(H + ((long long)j_node * S_SLOTS + s) * 2);

        float f[10];
        f[0] = c2 * hv.x - s2 * hv.y;
        f[1] = s2 * hv.x + c2 * hv.y;
        f[2] = gp[0]; f[3] = gp[1]; f[4] = gp[2];
        f[5] = gp[3]; f[6] = gp[4]; f[7] = s2; f[8] = c2; f[9] = gp[7];
        // rows beyond `items` have all-zero geometry (c2=s2=0 -> f0=f1=0): harmless.

        char* xh = smem + OFF_XHI + t * XPITCH;
        char* xl = smem + OFF_XLO + t * XPITCH;
        #pragma unroll
        for (int c = 0; c < 10; c += 2) {
            __nv_bfloat16 h0 = __float2bfloat16_rn(f[c]);
            __nv_bfloat16 h1 = __float2bfloat16_rn(f[c + 1]);
            *(uint32_t*)(xh + c * 2) = pack_bf2(__bfloat162float(h0), __bfloat162float(h1));
            *(uint32_t*)(xl + c * 2) = pack_bf2(f[c]     - __bfloat162float(h0),
                                                f[c + 1] - __bfloat162float(h1));
        }
        *(uint32_t*)(xh + 20) = 0u; *(uint32_t*)(xh + 24) = 0u; *(uint32_t*)(xh + 28) = 0u;
        *(uint32_t*)(xl + 20) = 0u; *(uint32_t*)(xl + 24) = 0u; *(uint32_t*)(xl + 28) = 0u;
    }
    __syncthreads();

    // ================= ldmatrix address precompute =================
    const int sel = lane >> 3;
    const int r8  = lane & 7;
    const uint32_t a_off  = (uint32_t)((w * 16 + r8 + (sel & 1) * 8) * XPITCH + (sel >> 1) * 16);
    const uint32_t w1_off = (uint32_t)(((sel >> 1) * 8 + r8) * WPITCH1 + (sel & 1) * 16);
    const uint32_t w2_off = (uint32_t)(((sel >> 1) * 8 + r8) * WPITCH2 + (sel & 1) * 16);

    // ================= layer 1: X(128x16) @ W1(16x64) =================
    float c1[32];
    #pragma unroll
    for (int i = 0; i < 32; i++) c1[i] = 0.0f;
    {
        uint32_t a1h[4], a1l[4];
        ldm4(sb + OFF_XHI + a_off, a1h[0], a1h[1], a1h[2], a1h[3]);
        ldm4(sb + OFF_XLO + a_off, a1l[0], a1l[1], a1l[2], a1l[3]);
        #pragma unroll
        for (int jp = 0; jp < 8; jp += 2) {
            uint32_t wh0, wh1, wh2, wh3, wl0, wl1, wl2, wl3;
            ldm4(sb + OFF_W1H + jp * 8 * WPITCH1 + w1_off, wh0, wh1, wh2, wh3);
            ldm4(sb + OFF_W1L + jp * 8 * WPITCH1 + w1_off, wl0, wl1, wl2, wl3);
            mma16816(c1 + 4 * jp,     a1h[0], a1h[1], a1h[2], a1h[3], wh0, wh1);
            mma16816(c1 + 4 * jp,     a1l[0], a1l[1], a1l[2], a1l[3], wh0, wh1);
            mma16816(c1 + 4 * jp,     a1h[0], a1h[1], a1h[2], a1h[3], wl0, wl1);
            mma16816(c1 + 4 * jp + 4, a1h[0], a1h[1], a1h[2], a1h[3], wh2, wh3);
            mma16816(c1 + 4 * jp + 4, a1l[0], a1l[1], a1l[2], a1l[3], wh2, wh3);
            mma16816(c1 + 4 * jp + 4, a1h[0], a1h[1], a1h[2], a1h[3], wl2, wl3);
        }
    }

    // ======== layer 2 with fused epilogue-1 (a2 frags live 8 regs only) ======
    const int cb = 2 * (lane & 3);
    float c2acc[32];
    #pragma unroll
    for (int i = 0; i < 32; i++) c2acc[i] = 0.0f;

    #pragma unroll
    for (int q = 0; q < 4; q++) {
        uint32_t a2h[4], a2l[4];
        #pragma unroll
        for (int jj = 0; jj < 2; jj++) {            // n-tiles j = 2q+jj
            const int cjj = 8 * q + 4 * jj;
            const float2 bia = *(const float2*)(smem + OFF_B1 + (8 * (2 * q + jj) + cb) * 4);
            float v0 = silu(c1[cjj + 0] + bia.x);
            float v1 = silu(c1[cjj + 1] + bia.y);
            float v2 = silu(c1[cjj + 2] + bia.x);
            float v3 = silu(c1[cjj + 3] + bia.y);
            __nv_bfloat16 h0 = __float2bfloat16_rn(v0), h1 = __float2bfloat16_rn(v1);
            __nv_bfloat16 h2 = __float2bfloat16_rn(v2), h3 = __float2bfloat16_rn(v3);
            a2h[2 * jj + 0] = pack_bf2(__bfloat162float(h0), __bfloat162float(h1));
            a2h[2 * jj + 1] = pack_bf2(__bfloat162float(h2), __bfloat162float(h3));
            a2l[2 * jj + 0] = pack_bf2(v0 - __bfloat162float(h0), v1 - __bfloat162float(h1));
            a2l[2 * jj + 1] = pack_bf2(v2 - __bfloat162float(h2), v3 - __bfloat162float(h3));
        }
        #pragma unroll
        for (int jp = 0; jp < 8; jp += 2) {
            uint32_t wh0, wh1, wh2, wh3, wl0, wl1, wl2, wl3;
            ldm4(sb + OFF_W2H + jp * 8 * WPITCH2 + q * 32 + w2_off, wh0, wh1, wh2, wh3);
            ldm4(sb + OFF_W2L + jp * 8 * WPITCH2 + q * 32 + w2_off, wl0, wl1, wl2, wl3);
            mma16816(c2acc + 4 * jp,     a2h[0], a2h[1], a2h[2], a2h[3], wh0, wh1);
            mma16816(c2acc + 4 * jp,     a2l[0], a2l[1], a2l[2], a2l[3], wh0, wh1);
            mma16816(c2acc + 4 * jp,     a2h[0], a2h[1], a2h[2], a2h[3], wl0, wl1);
            mma16816(c2acc + 4 * jp + 4, a2h[0], a2h[1], a2h[2], a2h[3], wh2, wh3);
            mma16816(c2acc + 4 * jp + 4, a2l[0], a2l[1], a2l[2], a2l[3], wh2, wh3);
            mma16816(c2acc + 4 * jp + 4, a2h[0], a2h[1], a2h[2], a2h[3], wl2, wl3);
        }
    }

    // ============ epilogue 2: bias + silu + layer3 + reduce + scatter ============
    float o0a = 0.f, o1a = 0.f, o0b = 0.f, o1b = 0.f;
    #pragma unroll
    for (int j = 0; j < 8; j++) {
        const int c0 = 8 * j + cb;
        const float2 bia = *(const float2*)(smem + OFF_B2 + c0 * 4);
        const float2 w3a = *(const float2*)(smem + OFF_W3 + c0 * 8);
        const float2 w3b = *(const float2*)(smem + OFF_W3 + (c0 + 1) * 8);
        float v0 = silu(c2acc[4 * j + 0] + bia.x);
        float v1 = silu(c2acc[4 * j + 1] + bia.y);
        float v2 = silu(c2acc[4 * j + 2] + bia.x);
        float v3 = silu(c2acc[4 * j + 3] + bia.y);
        o0a = fmaf(v0, w3a.x, fmaf(v1, w3b.x, o0a));
        o1a = fmaf(v0, w3a.y, fmaf(v1, w3b.y, o1a));
        o0b = fmaf(v2, w3a.x, fmaf(v3, w3b.x, o0b));
        o1b = fmaf(v2, w3a.y, fmaf(v3, w3b.y, o1b));
    }
    #pragma unroll
    for (int m = 1; m <= 2; m <<= 1) {
        o0a += __shfl_xor_sync(0xffffffffu, o0a, m);
        o1a += __shfl_xor_sync(0xffffffffu, o1a, m);
        o0b += __shfl_xor_sync(0xffffffffu, o0b, m);
        o1b += __shfl_xor_sync(0xffffffffu, o1b, m);
    }
    if ((lane & 3) == 0) {
        const float bb0 = ((float*)(smem + OFF_B3))[0];
        const float bb1 = ((float*)(smem + OFF_B3))[1];
        const int g = lane >> 2;
        #pragma unroll
        for (int half = 0; half < 2; half++) {
            const long long item = (long long)blockIdx.x * TILE + w * 16 + g + 8 * half;
            if (item < items) {
                const int e = (int)(item >> 2);
                const int s = (int)(item & 3);
                int i_node;
                if (is64) i_node = (int)((const long long*)edge)[e];
                else      i_node = edge[e];
                float* o = out + ((long long)i_node * S_SLOTS + s) * 2;
                atomicAdd(o + 0, (half ? o0b : o0a) + bb0);
                atomicAdd(o + 1, (half ? o1b : o1a) + bb1);
            }
        }
    }
}

extern "C" void kernel_launch(void* const* d_in, const int* in_sizes, int n_in,
                              void* d_out, int out_size) {
    const float* x     = (const float*)d_in[0];
    const float* theta = (const float*)d_in[1];
    const float* H     = (const float*)d_in[2];
    const int*   edge  = (const int*)d_in[3];
    const float* W1    = (const float*)d_in[4];
    const float* b1    = (const float*)d_in[5];
    const float* W2    = (const float*)d_in[6];
    const float* b2    = (const float*)d_in[7];
    const float* W3    = (const float*)d_in[8];
    const float* b3    = (const float*)d_in[9];

    const int nE = in_sizes[3] / 2;

    detect_edge_dtype_kernel<<<1, 32>>>(edge, in_sizes[3]);
    zero_out_kernel<<<(out_size + 255) / 256, 256>>>((float*)d_out, out_size);

    const long long items = (long long)nE * S_SLOTS;
    const int ntiles = (int)((items + TILE - 1) / TILE);
    gnn_mma_kernel<<<ntiles, NTHREADS>>>(x, theta, H, edge,
                                         W1, b1, W2, b2, W3, b3,
                                         (float*)d_out, nE);
}

// round 7
// speedup vs baseline: 2.9531x; 1.1250x over previous
#include <cuda_runtime.h>
#include <cuda_bf16.h>
#include <cstdint>

// FrameAlignedGNNLayer3D via mma.sync (sm_100-safe HMMA path).
// R7: (1) detect folded into init kernel -> 2 launches/call so ncu -s 5 -c 1
//     finally profiles the MAIN kernel; (2) silu via tanh.approx (1 MUFU
//     instead of 2: EX2+RCP -> TANH), halving the dominant modeled pipe.

#define S_SLOTS 4
#define TILE 128
#define NTHREADS 256

// ---- smem layout (static, <40KB) ----
#define XPITCH 48      // 16 bf16 (32B) + 16B pad -> conflict-free ldmatrix
#define WPITCH1 48
#define WPITCH2 144    // 64 bf16 (128B) + 16B pad
#define GPITCH 12      // floats per edge-geometry record
#define OFF_XHI  0
#define OFF_XLO  (OFF_XHI + 128 * XPITCH)      // 6144
#define OFF_W1H  (OFF_XLO + 128 * XPITCH)      // 12288
#define OFF_W1L  (OFF_W1H + 64 * WPITCH1)      // 15360
#define OFF_W2H  (OFF_W1L + 64 * WPITCH1)      // 18432
#define OFF_W2L  (OFF_W2H + 64 * WPITCH2)      // 27648
#define OFF_B1   (OFF_W2L + 64 * WPITCH2)      // 36864
#define OFF_B2   (OFF_B1 + 256)
#define OFF_W3   (OFF_B2 + 256)                // 64 float2 pairs
#define OFF_B3   (OFF_W3 + 512)
#define OFF_GEOM (OFF_B3 + 16)                 // 32 edges x 12 floats
#define SMEM_BYTES (OFF_GEOM + 32 * GPITCH * 4)

__device__ int g_edge_is_i64;

// init: zero the output AND detect edge dtype (block 0, thread 0).
// Keeps kernel_launch at exactly 2 launches so ncu's -s 5 -c 1 samples the
// main kernel (6th launch) instead of a helper.
__global__ void init_kernel(float* __restrict__ out, int n,
                            const int* __restrict__ edge32, int n32) {
    int idx = blockIdx.x * blockDim.x + threadIdx.x;
    if (idx < n) out[idx] = 0.0f;
    if (idx == 0) {
        int any_nonzero = 0;
        for (int s = 0; s < 16; s++) {
            long long pos = 1 + (long long)s * ((n32 - 2) / 16);
            pos |= 1;
            if (pos < n32) any_nonzero |= (edge32[pos] != 0);
        }
        g_edge_is_i64 = any_nonzero ? 0 : 1;
    }
}

// silu via hardware tanh: silu(v) = 0.5v * (1 + tanh(0.5v)).
// 1 MUFU (TANH) + 2 FMA vs EX2+RCP (2 MUFU) before.
__device__ __forceinline__ float silu(float v) {
    float h = 0.5f * v;
    float t;
    asm("tanh.approx.f32 %0, %1;" : "=f"(t) : "f"(h));
    return fmaf(h, t, h);
}

__device__ __forceinline__ uint32_t smem_u32(const void* p) {
    uint32_t a;
    asm("{ .reg .u64 t; cvta.to.shared.u64 t, %1; cvt.u32.u64 %0, t; }" : "=r"(a) : "l"(p));
    return a;
}

__device__ __forceinline__ void ldm4(uint32_t addr, uint32_t& r0, uint32_t& r1,
                                     uint32_t& r2, uint32_t& r3) {
    asm volatile("ldmatrix.sync.aligned.m8n8.x4.shared.b16 {%0,%1,%2,%3}, [%4];"
                 : "=r"(r0), "=r"(r1), "=r"(r2), "=r"(r3) : "r"(addr));
}

__device__ __forceinline__ void mma16816(float* c, uint32_t a0, uint32_t a1,
                                         uint32_t a2, uint32_t a3,
                                         uint32_t b0, uint32_t b1) {
    asm volatile(
        "mma.sync.aligned.m16n8k16.row.col.f32.bf16.bf16.f32 "
        "{%0,%1,%2,%3}, {%4,%5,%6,%7}, {%8,%9}, {%0,%1,%2,%3};"
        : "+f"(c[0]), "+f"(c[1]), "+f"(c[2]), "+f"(c[3])
        : "r"(a0), "r"(a1), "r"(a2), "r"(a3), "r"(b0), "r"(b1));
}

__device__ __forceinline__ uint32_t pack_bf2(float v0, float v1) {
    __nv_bfloat162 p = __floats2bfloat162_rn(v0, v1);   // .x = v0 (low half)
    return *reinterpret_cast<uint32_t*>(&p);
}

__global__ __launch_bounds__(NTHREADS, 2)
void gnn_mma_kernel(
    const float* __restrict__ x, const float* __restrict__ theta,
    const float* __restrict__ H, const int* __restrict__ edge,
    const float* __restrict__ W1, const float* __restrict__ b1,
    const float* __restrict__ W2, const float* __restrict__ b2,
    const float* __restrict__ W3, const float* __restrict__ b3,
    float* __restrict__ out, int nE)
{
    __shared__ __align__(16) char smem[SMEM_BYTES];
    const uint32_t sb = smem_u32(smem);

    const int t    = threadIdx.x;
    const int lane = t & 31;
    const int w    = t >> 5;           // warp id, rows [16w, 16w+16)
    const int is64 = g_edge_is_i64;
    const long long items = (long long)nE * S_SLOTS;

    // ================= stage weights =================
    for (int idx = t; idx < 64 * 10; idx += NTHREADS) {
        int kk = idx / 64, n = idx % 64;
        float v = W1[kk * 64 + n];
        __nv_bfloat16 hi = __float2bfloat16_rn(v);
        __nv_bfloat16 lo = __float2bfloat16_rn(v - __bfloat162float(hi));
        *(__nv_bfloat16*)(smem + OFF_W1H + n * WPITCH1 + kk * 2) = hi;
        *(__nv_bfloat16*)(smem + OFF_W1L + n * WPITCH1 + kk * 2) = lo;
    }
    if (t < 64) {  // zero pad kk 10..15 of W1
        for (int kk = 10; kk < 16; kk++) {
            *(__nv_bfloat16*)(smem + OFF_W1H + t * WPITCH1 + kk * 2) = __float2bfloat16_rn(0.f);
            *(__nv_bfloat16*)(smem + OFF_W1L + t * WPITCH1 + kk * 2) = __float2bfloat16_rn(0.f);
        }
    }
    for (int idx = t; idx < 64 * 64; idx += NTHREADS) {
        int k = idx >> 6, n = idx & 63;
        float v = W2[k * 64 + n];
        __nv_bfloat16 hi = __float2bfloat16_rn(v);
        __nv_bfloat16 lo = __float2bfloat16_rn(v - __bfloat162float(hi));
        *(__nv_bfloat16*)(smem + OFF_W2H + n * WPITCH2 + k * 2) = hi;
        *(__nv_bfloat16*)(smem + OFF_W2L + n * WPITCH2 + k * 2) = lo;
    }
    if (t < 64) {
        ((float*)(smem + OFF_B1))[t] = b1[t];
        ((float*)(smem + OFF_B2))[t] = b2[t];
        ((float2*)(smem + OFF_W3))[t] = make_float2(W3[2 * t], W3[2 * t + 1]);
    }
    if (t < 2) ((float*)(smem + OFF_B3))[t] = b3[t];

    // ================= per-edge geometry (warp 0, 32 edges/tile) =============
    if (t < 32) {
        const long long e = (long long)blockIdx.x * 32 + t;
        float g0 = 0.f, g1 = 0.f, g2 = 0.f, g3 = 0.f,
              g4 = 0.f, g5 = 0.f, g6 = 0.f, g7 = 0.f;
        int j_node = 0;
        if (e < nE) {
            int i_node;
            if (is64) {
                const long long* e64 = (const long long*)edge;
                i_node = (int)e64[e]; j_node = (int)e64[(long long)nE + e];
            } else {
                i_node = edge[e]; j_node = edge[nE + e];
            }
            const float dx0 = x[3 * j_node + 0] - x[3 * i_node + 0];
            const float dx1 = x[3 * j_node + 1] - x[3 * i_node + 1];
            const float dx2 = x[3 * j_node + 2] - x[3 * i_node + 2];
            const float rxy2 = dx0 * dx0 + dx1 * dx1;
            const float ti = theta[i_node], tj = theta[j_node];
            float s2, c2; sincosf(2.0f * (tj - ti), &s2, &c2);
            float sp, cp; sincosf(atan2f(dx1, dx0) - ti, &sp, &cp);
            const float sgn = (dx2 > 0.0f) ? 1.0f : ((dx2 < 0.0f) ? -1.0f : 0.0f);
            g0 = sqrtf(rxy2 + dx2 * dx2);  // r3d
            g1 = sqrtf(rxy2);              // rxy
            g2 = dx2;
            g3 = sp;  g4 = cp;
            g5 = s2;  g6 = c2;
            g7 = sgn * s2;
        }
        float* gp = (float*)(smem + OFF_GEOM) + t * GPITCH;
        gp[0] = g0; gp[1] = g1; gp[2] = g2; gp[3] = g3;
        gp[4] = g4; gp[5] = g5; gp[6] = g6; gp[7] = g7;
        ((int*)gp)[8] = j_node;
    }
    __syncthreads();

    // ================= per-row features (t < 128) =================
    if (t < TILE) {
        const int e_loc = t >> 2;
        const int s     = t & 3;
        const float* gp = (const float*)(smem + OFF_GEOM) + e_loc * GPITCH;
        const float s2 = gp[5], c2 = gp[6];
        const int j_node = ((const int*)gp)[8];
        const float2 hv = *(const float2*)(H + ((long long)j_node * S_SLOTS + s) * 2);

        float f[10];
        f[0] = c2 * hv.x - s2 * hv.y;
        f[1] = s2 * hv.x + c2 * hv.y;
        f[2] = gp[0]; f[3] = gp[1]; f[4] = gp[2];
        f[5] = gp[3]; f[6] = gp[4]; f[7] = s2; f[8] = c2; f[9] = gp[7];
        // rows beyond `items` have all-zero geometry (c2=s2=0 -> f0=f1=0): harmless.

        char* xh = smem + OFF_XHI + t * XPITCH;
        char* xl = smem + OFF_XLO + t * XPITCH;
        #pragma unroll
        for (int c = 0; c < 10; c += 2) {
            __nv_bfloat16 h0 = __float2bfloat16_rn(f[c]);
            __nv_bfloat16 h1 = __float2bfloat16_rn(f[c + 1]);
            *(uint32_t*)(xh + c * 2) = pack_bf2(__bfloat162float(h0), __bfloat162float(h1));
            *(uint32_t*)(xl + c * 2) = pack_bf2(f[c]     - __bfloat162float(h0),
                                                f[c + 1] - __bfloat162float(h1));
        }
        *(uint32_t*)(xh + 20) = 0u; *(uint32_t*)(xh + 24) = 0u; *(uint32_t*)(xh + 28) = 0u;
        *(uint32_t*)(xl + 20) = 0u; *(uint32_t*)(xl + 24) = 0u; *(uint32_t*)(xl + 28) = 0u;
    }
    __syncthreads();

    // ================= ldmatrix address precompute =================
    const int sel = lane >> 3;
    const int r8  = lane & 7;
    const uint32_t a_off  = (uint32_t)((w * 16 + r8 + (sel & 1) * 8) * XPITCH + (sel >> 1) * 16);
    const uint32_t w1_off = (uint32_t)(((sel >> 1) * 8 + r8) * WPITCH1 + (sel & 1) * 16);
    const uint32_t w2_off = (uint32_t)(((sel >> 1) * 8 + r8) * WPITCH2 + (sel & 1) * 16);

    // ================= layer 1: X(128x16) @ W1(16x64) =================
    float c1[32];
    #pragma unroll
    for (int i = 0; i < 32; i++) c1[i] = 0.0f;
    {
        uint32_t a1h[4], a1l[4];
        ldm4(sb + OFF_XHI + a_off, a1h[0], a1h[1], a1h[2], a1h[3]);
        ldm4(sb + OFF_XLO + a_off, a1l[0], a1l[1], a1l[2], a1l[3]);
        #pragma unroll
        for (int jp = 0; jp < 8; jp += 2) {
            uint32_t wh0, wh1, wh2, wh3, wl0, wl1, wl2, wl3;
            ldm4(sb + OFF_W1H + jp * 8 * WPITCH1 + w1_off, wh0, wh1, wh2, wh3);
            ldm4(sb + OFF_W1L + jp * 8 * WPITCH1 + w1_off, wl0, wl1, wl2, wl3);
            mma16816(c1 + 4 * jp,     a1h[0], a1h[1], a1h[2], a1h[3], wh0, wh1);
            mma16816(c1 + 4 * jp,     a1l[0], a1l[1], a1l[2], a1l[3], wh0, wh1);
            mma16816(c1 + 4 * jp,     a1h[0], a1h[1], a1h[2], a1h[3], wl0, wl1);
            mma16816(c1 + 4 * jp + 4, a1h[0], a1h[1], a1h[2], a1h[3], wh2, wh3);
            mma16816(c1 + 4 * jp + 4, a1l[0], a1l[1], a1l[2], a1l[3], wh2, wh3);
            mma16816(c1 + 4 * jp + 4, a1h[0], a1h[1], a1h[2], a1h[3], wl2, wl3);
        }
    }

    // ======== layer 2 with fused epilogue-1 (a2 frags live 8 regs only) ======
    const int cb = 2 * (lane & 3);
    float c2acc[32];
    #pragma unroll
    for (int i = 0; i < 32; i++) c2acc[i] = 0.0f;

    #pragma unroll
    for (int q = 0; q < 4; q++) {
        uint32_t a2h[4], a2l[4];
        #pragma unroll
        for (int jj = 0; jj < 2; jj++) {            // n-tiles j = 2q+jj
            const int cjj = 8 * q + 4 * jj;
            const float2 bia = *(const float2*)(smem + OFF_B1 + (8 * (2 * q + jj) + cb) * 4);
            float v0 = silu(c1[cjj + 0] + bia.x);
            float v1 = silu(c1[cjj + 1] + bia.y);
            float v2 = silu(c1[cjj + 2] + bia.x);
            float v3 = silu(c1[cjj + 3] + bia.y);
            __nv_bfloat16 h0 = __float2bfloat16_rn(v0), h1 = __float2bfloat16_rn(v1);
            __nv_bfloat16 h2 = __float2bfloat16_rn(v2), h3 = __float2bfloat16_rn(v3);
            a2h[2 * jj + 0] = pack_bf2(__bfloat162float(h0), __bfloat162float(h1));
            a2h[2 * jj + 1] = pack_bf2(__bfloat162float(h2), __bfloat162float(h3));
            a2l[2 * jj + 0] = pack_bf2(v0 - __bfloat162float(h0), v1 - __bfloat162float(h1));
            a2l[2 * jj + 1] = pack_bf2(v2 - __bfloat162float(h2), v3 - __bfloat162float(h3));
        }
        #pragma unroll
        for (int jp = 0; jp < 8; jp += 2) {
            uint32_t wh0, wh1, wh2, wh3, wl0, wl1, wl2, wl3;
            ldm4(sb + OFF_W2H + jp * 8 * WPITCH2 + q * 32 + w2_off, wh0, wh1, wh2, wh3);
            ldm4(sb + OFF_W2L + jp * 8 * WPITCH2 + q * 32 + w2_off, wl0, wl1, wl2, wl3);
            mma16816(c2acc + 4 * jp,     a2h[0], a2h[1], a2h[2], a2h[3], wh0, wh1);
            mma16816(c2acc + 4 * jp,     a2l[0], a2l[1], a2l[2], a2l[3], wh0, wh1);
            mma16816(c2acc + 4 * jp,     a2h[0], a2h[1], a2h[2], a2h[3], wl0, wl1);
            mma16816(c2acc + 4 * jp + 4, a2h[0], a2h[1], a2h[2], a2h[3], wh2, wh3);
            mma16816(c2acc + 4 * jp + 4, a2l[0], a2l[1], a2l[2], a2l[3], wh2, wh3);
            mma16816(c2acc + 4 * jp + 4, a2h[0], a2h[1], a2h[2], a2h[3], wl2, wl3);
        }
    }

    // ============ epilogue 2: bias + silu + layer3 + reduce + scatter ============
    float o0a = 0.f, o1a = 0.f, o0b = 0.f, o1b = 0.f;
    #pragma unroll
    for (int j = 0; j < 8; j++) {
        const int c0 = 8 * j + cb;
        const float2 bia = *(const float2*)(smem + OFF_B2 + c0 * 4);
        const float2 w3a = *(const float2*)(smem + OFF_W3 + c0 * 8);
        const float2 w3b = *(const float2*)(smem + OFF_W3 + (c0 + 1) * 8);
        float v0 = silu(c2acc[4 * j + 0] + bia.x);
        float v1 = silu(c2acc[4 * j + 1] + bia.y);
        float v2 = silu(c2acc[4 * j + 2] + bia.x);
        float v3 = silu(c2acc[4 * j + 3] + bia.y);
        o0a = fmaf(v0, w3a.x, fmaf(v1, w3b.x, o0a));
        o1a = fmaf(v0, w3a.y, fmaf(v1, w3b.y, o1a));
        o0b = fmaf(v2, w3a.x, fmaf(v3, w3b.x, o0b));
        o1b = fmaf(v2, w3a.y, fmaf(v3, w3b.y, o1b));
    }
    #pragma unroll
    for (int m = 1; m <= 2; m <<= 1) {
        o0a += __shfl_xor_sync(0xffffffffu, o0a, m);
        o1a += __shfl_xor_sync(0xffffffffu, o1a, m);
        o0b += __shfl_xor_sync(0xffffffffu, o0b, m);
        o1b += __shfl_xor_sync(0xffffffffu, o1b, m);
    }
    if ((lane & 3) == 0) {
        const float bb0 = ((float*)(smem + OFF_B3))[0];
        const float bb1 = ((float*)(smem + OFF_B3))[1];
        const int g = lane >> 2;
        #pragma unroll
        for (int half = 0; half < 2; half++) {
            const long long item = (long long)blockIdx.x * TILE + w * 16 + g + 8 * half;
            if (item < items) {
                const int e = (int)(item >> 2);
                const int s = (int)(item & 3);
                int i_node;
                if (is64) i_node = (int)((const long long*)edge)[e];
                else      i_node = edge[e];
                float* o = out + ((long long)i_node * S_SLOTS + s) * 2;
                atomicAdd(o + 0, (half ? o0b : o0a) + bb0);
                atomicAdd(o + 1, (half ? o1b : o1a) + bb1);
            }
        }
    }
}

extern "C" void kernel_launch(void* const* d_in, const int* in_sizes, int n_in,
                              void* d_out, int out_size) {
    const float* x     = (const float*)d_in[0];
    const float* theta = (const float*)d_in[1];
    const float* H     = (const float*)d_in[2];
    const int*   edge  = (const int*)d_in[3];
    const float* W1    = (const float*)d_in[4];
    const float* b1    = (const float*)d_in[5];
    const float* W2    = (const float*)d_in[6];
    const float* b2    = (const float*)d_in[7];
    const float* W3    = (const float*)d_in[8];
    const float* b3    = (const float*)d_in[9];

    const int nE = in_sizes[3] / 2;

    init_kernel<<<(out_size + 255) / 256, 256>>>((float*)d_out, out_size,
                                                 edge, in_sizes[3]);

    const long long items = (long long)nE * S_SLOTS;
    const int ntiles = (int)((items + TILE - 1) / TILE);
    gnn_mma_kernel<<<ntiles, NTHREADS>>>(x, theta, H, edge,
                                         W1, b1, W2, b2, W3, b3,
                                         (float*)d_out, nE);
}

// round 8
// speedup vs baseline: 4.0640x; 1.3762x over previous
#include <cuda_runtime.h>
#include <cuda_bf16.h>
#include <cstdint>

// FrameAlignedGNNLayer3D via mma.sync (sm_100-safe HMMA path).
// R8: PERSISTENT blocks (grid = 2*SMs). Weights are split/staged to smem ONCE
// per block instead of once per 128-row tile (25,000x before) — removes the
// dominant L1 traffic (staging STS w/ 4-way conflicts) and the split-cvt ALU
// load identified in the R7 profile (L1=64%, ALU=18%).
// Feature geometry computed redundantly per quad (no GEOM smem, 2 barriers/tile).

#define S_SLOTS 4
#define TILE 128
#define NTHREADS 256

// ---- smem layout (static, ~37KB) ----
#define XPITCH 48      // 16 bf16 (32B) + 16B pad -> conflict-free ldmatrix
#define WPITCH1 48
#define WPITCH2 144    // 64 bf16 (128B) + 16B pad
#define OFF_XHI  0
#define OFF_XLO  (OFF_XHI + 128 * XPITCH)      // 6144
#define OFF_W1H  (OFF_XLO + 128 * XPITCH)      // 12288
#define OFF_W1L  (OFF_W1H + 64 * WPITCH1)      // 15360
#define OFF_W2H  (OFF_W1L + 64 * WPITCH1)      // 18432
#define OFF_W2L  (OFF_W2H + 64 * WPITCH2)      // 27648
#define OFF_B1   (OFF_W2L + 64 * WPITCH2)      // 36864
#define OFF_B2   (OFF_B1 + 256)
#define OFF_W3   (OFF_B2 + 256)                // 64 float2 pairs
#define OFF_B3   (OFF_W3 + 512)
#define SMEM_BYTES (OFF_B3 + 16)

__device__ int g_edge_is_i64;

// init: zero output AND detect edge dtype. Keeps kernel_launch at exactly
// 2 launches so ncu -s 5 -c 1 profiles the main kernel.
__global__ void init_kernel(float* __restrict__ out, int n,
                            const int* __restrict__ edge32, int n32) {
    int idx = blockIdx.x * blockDim.x + threadIdx.x;
    if (idx < n) out[idx] = 0.0f;
    if (idx == 0) {
        int any_nonzero = 0;
        for (int s = 0; s < 16; s++) {
            long long pos = 1 + (long long)s * ((n32 - 2) / 16);
            pos |= 1;
            if (pos < n32) any_nonzero |= (edge32[pos] != 0);
        }
        g_edge_is_i64 = any_nonzero ? 0 : 1;
    }
}

// silu via hardware tanh: silu(v) = 0.5v * (1 + tanh(0.5v)). 1 MUFU + 2 FMA.
__device__ __forceinline__ float silu(float v) {
    float h = 0.5f * v;
    float t;
    asm("tanh.approx.f32 %0, %1;" : "=f"(t) : "f"(h));
    return fmaf(h, t, h);
}

__device__ __forceinline__ uint32_t smem_u32(const void* p) {
    uint32_t a;
    asm("{ .reg .u64 t; cvta.to.shared.u64 t, %1; cvt.u32.u64 %0, t; }" : "=r"(a) : "l"(p));
    return a;
}

__device__ __forceinline__ void ldm4(uint32_t addr, uint32_t& r0, uint32_t& r1,
                                     uint32_t& r2, uint32_t& r3) {
    asm volatile("ldmatrix.sync.aligned.m8n8.x4.shared.b16 {%0,%1,%2,%3}, [%4];"
                 : "=r"(r0), "=r"(r1), "=r"(r2), "=r"(r3) : "r"(addr));
}

__device__ __forceinline__ void mma16816(float* c, uint32_t a0, uint32_t a1,
                                         uint32_t a2, uint32_t a3,
                                         uint32_t b0, uint32_t b1) {
    asm volatile(
        "mma.sync.aligned.m16n8k16.row.col.f32.bf16.bf16.f32 "
        "{%0,%1,%2,%3}, {%4,%5,%6,%7}, {%8,%9}, {%0,%1,%2,%3};"
        : "+f"(c[0]), "+f"(c[1]), "+f"(c[2]), "+f"(c[3])
        : "r"(a0), "r"(a1), "r"(a2), "r"(a3), "r"(b0), "r"(b1));
}

__device__ __forceinline__ uint32_t pack_bf2(float v0, float v1) {
    __nv_bfloat162 p = __floats2bfloat162_rn(v0, v1);   // .x = v0 (low half)
    return *reinterpret_cast<uint32_t*>(&p);
}

__global__ __launch_bounds__(NTHREADS, 2)
void gnn_mma_kernel(
    const float* __restrict__ x, const float* __restrict__ theta,
    const float* __restrict__ H, const int* __restrict__ edge,
    const float* __restrict__ W1, const float* __restrict__ b1,
    const float* __restrict__ W2, const float* __restrict__ b2,
    const float* __restrict__ W3, const float* __restrict__ b3,
    float* __restrict__ out, int nE, int ntiles)
{
    __shared__ __align__(16) char smem[SMEM_BYTES];
    const uint32_t sb = smem_u32(smem);

    const int t    = threadIdx.x;
    const int lane = t & 31;
    const int w    = t >> 5;           // warp id, rows [16w, 16w+16)
    const int is64 = g_edge_is_i64;
    const long long items = (long long)nE * S_SLOTS;

    // ================= stage weights ONCE per block =================
    for (int idx = t; idx < 64 * 10; idx += NTHREADS) {
        int kk = idx / 64, n = idx % 64;
        float v = W1[kk * 64 + n];
        __nv_bfloat16 hi = __float2bfloat16_rn(v);
        __nv_bfloat16 lo = __float2bfloat16_rn(v - __bfloat162float(hi));
        *(__nv_bfloat16*)(smem + OFF_W1H + n * WPITCH1 + kk * 2) = hi;
        *(__nv_bfloat16*)(smem + OFF_W1L + n * WPITCH1 + kk * 2) = lo;
    }
    if (t < 64) {  // zero pad kk 10..15 of W1
        for (int kk = 10; kk < 16; kk++) {
            *(__nv_bfloat16*)(smem + OFF_W1H + t * WPITCH1 + kk * 2) = __float2bfloat16_rn(0.f);
            *(__nv_bfloat16*)(smem + OFF_W1L + t * WPITCH1 + kk * 2) = __float2bfloat16_rn(0.f);
        }
    }
    for (int idx = t; idx < 64 * 64; idx += NTHREADS) {
        int k = idx >> 6, n = idx & 63;
        float v = W2[k * 64 + n];
        __nv_bfloat16 hi = __float2bfloat16_rn(v);
        __nv_bfloat16 lo = __float2bfloat16_rn(v - __bfloat162float(hi));
        *(__nv_bfloat16*)(smem + OFF_W2H + n * WPITCH2 + k * 2) = hi;
        *(__nv_bfloat16*)(smem + OFF_W2L + n * WPITCH2 + k * 2) = lo;
    }
    if (t < 64) {
        ((float*)(smem + OFF_B1))[t] = b1[t];
        ((float*)(smem + OFF_B2))[t] = b2[t];
        ((float2*)(smem + OFF_W3))[t] = make_float2(W3[2 * t], W3[2 * t + 1]);
    }
    if (t < 2) ((float*)(smem + OFF_B3))[t] = b3[t];

    // ================= ldmatrix address precompute =================
    const int sel = lane >> 3;
    const int r8  = lane & 7;
    const uint32_t a_off  = (uint32_t)((w * 16 + r8 + (sel & 1) * 8) * XPITCH + (sel >> 1) * 16);
    const uint32_t w1_off = (uint32_t)(((sel >> 1) * 8 + r8) * WPITCH1 + (sel & 1) * 16);
    const uint32_t w2_off = (uint32_t)(((sel >> 1) * 8 + r8) * WPITCH2 + (sel & 1) * 16);
    const int cb = 2 * (lane & 3);

    __syncthreads();

    // ================= persistent tile loop =================
    for (int tile = blockIdx.x; tile < ntiles; tile += gridDim.x) {

        // ---- features (t < 128): geometry computed redundantly per quad ----
        if (t < TILE) {
            const long long item = (long long)tile * TILE + t;
            float f[10] = {0, 0, 0, 0, 0, 0, 0, 0, 0, 0};
            if (item < items) {
                const int e = (int)(item >> 2);
                const int s = (int)(item & 3);
                int i_node, j_node;
                if (is64) {
                    const long long* e64 = (const long long*)edge;
                    i_node = (int)e64[e]; j_node = (int)e64[(long long)nE + e];
                } else {
                    i_node = edge[e]; j_node = edge[nE + e];
                }
                const float dx0 = x[3 * j_node + 0] - x[3 * i_node + 0];
                const float dx1 = x[3 * j_node + 1] - x[3 * i_node + 1];
                const float dx2 = x[3 * j_node + 2] - x[3 * i_node + 2];
                const float rxy2 = dx0 * dx0 + dx1 * dx1;
                const float ti = theta[i_node], tj = theta[j_node];
                float s2, c2; sincosf(2.0f * (tj - ti), &s2, &c2);
                float sp, cp; sincosf(atan2f(dx1, dx0) - ti, &sp, &cp);
                const float sgn = (dx2 > 0.0f) ? 1.0f : ((dx2 < 0.0f) ? -1.0f : 0.0f);
                const float2 hv = *(const float2*)(H + ((long long)j_node * S_SLOTS + s) * 2);
                f[0] = c2 * hv.x - s2 * hv.y;
                f[1] = s2 * hv.x + c2 * hv.y;
                f[2] = sqrtf(rxy2 + dx2 * dx2);
                f[3] = sqrtf(rxy2);
                f[4] = dx2;
                f[5] = sp;  f[6] = cp;  f[7] = s2;  f[8] = c2;  f[9] = sgn * s2;
            }
            char* xh = smem + OFF_XHI + t * XPITCH;
            char* xl = smem + OFF_XLO + t * XPITCH;
            #pragma unroll
            for (int c = 0; c < 10; c += 2) {
                __nv_bfloat16 h0 = __float2bfloat16_rn(f[c]);
                __nv_bfloat16 h1 = __float2bfloat16_rn(f[c + 1]);
                *(uint32_t*)(xh + c * 2) = pack_bf2(__bfloat162float(h0), __bfloat162float(h1));
                *(uint32_t*)(xl + c * 2) = pack_bf2(f[c]     - __bfloat162float(h0),
                                                    f[c + 1] - __bfloat162float(h1));
            }
            *(uint32_t*)(xh + 20) = 0u; *(uint32_t*)(xh + 24) = 0u; *(uint32_t*)(xh + 28) = 0u;
            *(uint32_t*)(xl + 20) = 0u; *(uint32_t*)(xl + 24) = 0u; *(uint32_t*)(xl + 28) = 0u;
        }
        __syncthreads();

        // ---- layer 1: X(128x16) @ W1(16x64) ----
        float c1[32];
        #pragma unroll
        for (int i = 0; i < 32; i++) c1[i] = 0.0f;
        {
            uint32_t a1h[4], a1l[4];
            ldm4(sb + OFF_XHI + a_off, a1h[0], a1h[1], a1h[2], a1h[3]);
            ldm4(sb + OFF_XLO + a_off, a1l[0], a1l[1], a1l[2], a1l[3]);
            #pragma unroll
            for (int jp = 0; jp < 8; jp += 2) {
                uint32_t wh0, wh1, wh2, wh3, wl0, wl1, wl2, wl3;
                ldm4(sb + OFF_W1H + jp * 8 * WPITCH1 + w1_off, wh0, wh1, wh2, wh3);
                ldm4(sb + OFF_W1L + jp * 8 * WPITCH1 + w1_off, wl0, wl1, wl2, wl3);
                mma16816(c1 + 4 * jp,     a1h[0], a1h[1], a1h[2], a1h[3], wh0, wh1);
                mma16816(c1 + 4 * jp,     a1l[0], a1l[1], a1l[2], a1l[3], wh0, wh1);
                mma16816(c1 + 4 * jp,     a1h[0], a1h[1], a1h[2], a1h[3], wl0, wl1);
                mma16816(c1 + 4 * jp + 4, a1h[0], a1h[1], a1h[2], a1h[3], wh2, wh3);
                mma16816(c1 + 4 * jp + 4, a1l[0], a1l[1], a1l[2], a1l[3], wh2, wh3);
                mma16816(c1 + 4 * jp + 4, a1h[0], a1h[1], a1h[2], a1h[3], wl2, wl3);
            }
        }

        // ---- layer 2 with fused epilogue-1 (a2 frags live 8 regs only) ----
        float c2acc[32];
        #pragma unroll
        for (int i = 0; i < 32; i++) c2acc[i] = 0.0f;

        #pragma unroll
        for (int q = 0; q < 4; q++) {
            uint32_t a2h[4], a2l[4];
            #pragma unroll
            for (int jj = 0; jj < 2; jj++) {            // n-tiles j = 2q+jj
                const int cjj = 8 * q + 4 * jj;
                const float2 bia = *(const float2*)(smem + OFF_B1 + (8 * (2 * q + jj) + cb) * 4);
                float v0 = silu(c1[cjj + 0] + bia.x);
                float v1 = silu(c1[cjj + 1] + bia.y);
                float v2 = silu(c1[cjj + 2] + bia.x);
                float v3 = silu(c1[cjj + 3] + bia.y);
                __nv_bfloat16 h0 = __float2bfloat16_rn(v0), h1 = __float2bfloat16_rn(v1);
                __nv_bfloat16 h2 = __float2bfloat16_rn(v2), h3 = __float2bfloat16_rn(v3);
                a2h[2 * jj + 0] = pack_bf2(__bfloat162float(h0), __bfloat162float(h1));
                a2h[2 * jj + 1] = pack_bf2(__bfloat162float(h2), __bfloat162float(h3));
                a2l[2 * jj + 0] = pack_bf2(v0 - __bfloat162float(h0), v1 - __bfloat162float(h1));
                a2l[2 * jj + 1] = pack_bf2(v2 - __bfloat162float(h2), v3 - __bfloat162float(h3));
            }
            #pragma unroll
            for (int jp = 0; jp < 8; jp += 2) {
                uint32_t wh0, wh1, wh2, wh3, wl0, wl1, wl2, wl3;
                ldm4(sb + OFF_W2H + jp * 8 * WPITCH2 + q * 32 + w2_off, wh0, wh1, wh2, wh3);
                ldm4(sb + OFF_W2L + jp * 8 * WPITCH2 + q * 32 + w2_off, wl0, wl1, wl2, wl3);
                mma16816(c2acc + 4 * jp,     a2h[0], a2h[1], a2h[2], a2h[3], wh0, wh1);
                mma16816(c2acc + 4 * jp,     a2l[0], a2l[1], a2l[2], a2l[3], wh0, wh1);
                mma16816(c2acc + 4 * jp,     a2h[0], a2h[1], a2h[2], a2h[3], wl0, wl1);
                mma16816(c2acc + 4 * jp + 4, a2h[0], a2h[1], a2h[2], a2h[3], wh2, wh3);
                mma16816(c2acc + 4 * jp + 4, a2l[0], a2l[1], a2l[2], a2l[3], wh2, wh3);
                mma16816(c2acc + 4 * jp + 4, a2h[0], a2h[1], a2h[2], a2h[3], wl2, wl3);
            }
        }

        // ---- epilogue 2: bias + silu + layer3 + quad reduce + scatter ----
        float o0a = 0.f, o1a = 0.f, o0b = 0.f, o1b = 0.f;
        #pragma unroll
        for (int j = 0; j < 8; j++) {
            const int c0 = 8 * j + cb;
            const float2 bia = *(const float2*)(smem + OFF_B2 + c0 * 4);
            const float2 w3a = *(const float2*)(smem + OFF_W3 + c0 * 8);
            const float2 w3b = *(const float2*)(smem + OFF_W3 + (c0 + 1) * 8);
            float v0 = silu(c2acc[4 * j + 0] + bia.x);
            float v1 = silu(c2acc[4 * j + 1] + bia.y);
            float v2 = silu(c2acc[4 * j + 2] + bia.x);
            float v3 = silu(c2acc[4 * j + 3] + bia.y);
            o0a = fmaf(v0, w3a.x, fmaf(v1, w3b.x, o0a));
            o1a = fmaf(v0, w3a.y, fmaf(v1, w3b.y, o1a));
            o0b = fmaf(v2, w3a.x, fmaf(v3, w3b.x, o0b));
            o1b = fmaf(v2, w3a.y, fmaf(v3, w3b.y, o1b));
        }
        #pragma unroll
        for (int m = 1; m <= 2; m <<= 1) {
            o0a += __shfl_xor_sync(0xffffffffu, o0a, m);
            o1a += __shfl_xor_sync(0xffffffffu, o1a, m);
            o0b += __shfl_xor_sync(0xffffffffu, o0b, m);
            o1b += __shfl_xor_sync(0xffffffffu, o1b, m);
        }
        if ((lane & 3) == 0) {
            const float bb0 = ((float*)(smem + OFF_B3))[0];
            const float bb1 = ((float*)(smem + OFF_B3))[1];
            const int g = lane >> 2;
            #pragma unroll
            for (int half = 0; half < 2; half++) {
                const long long item = (long long)tile * TILE + w * 16 + g + 8 * half;
                if (item < items) {
                    const int e = (int)(item >> 2);
                    const int s = (int)(item & 3);
                    int i_node;
                    if (is64) i_node = (int)((const long long*)edge)[e];
                    else      i_node = edge[e];
                    float* o = out + ((long long)i_node * S_SLOTS + s) * 2;
                    atomicAdd(o + 0, (half ? o0b : o0a) + bb0);
                    atomicAdd(o + 1, (half ? o1b : o1a) + bb1);
                }
            }
        }
        __syncthreads();   // protect X tiles before next iteration's writes
    }
}

extern "C" void kernel_launch(void* const* d_in, const int* in_sizes, int n_in,
                              void* d_out, int out_size) {
    const float* x     = (const float*)d_in[0];
    const float* theta = (const float*)d_in[1];
    const float* H     = (const float*)d_in[2];
    const int*   edge  = (const int*)d_in[3];
    const float* W1    = (const float*)d_in[4];
    const float* b1    = (const float*)d_in[5];
    const float* W2    = (const float*)d_in[6];
    const float* b2    = (const float*)d_in[7];
    const float* W3    = (const float*)d_in[8];
    const float* b3    = (const float*)d_in[9];

    const int nE = in_sizes[3] / 2;

    init_kernel<<<(out_size + 255) / 256, 256>>>((float*)d_out, out_size,
                                                 edge, in_sizes[3]);

    const long long items = (long long)nE * S_SLOTS;
    const int ntiles = (int)((items + TILE - 1) / TILE);
    int grid = 2 * 148;                    // 2 persistent CTAs per SM
    if (grid > ntiles) grid = ntiles;
    gnn_mma_kernel<<<grid, NTHREADS>>>(x, theta, H, edge,
                                       W1, b1, W2, b2, W3, b3,
                                       (float*)d_out, nE, ntiles);
}

// round 9
// speedup vs baseline: 4.1350x; 1.0175x over previous
#include <cuda_runtime.h>
#include <cuda_bf16.h>
#include <cstdint>

// FrameAlignedGNNLayer3D via mma.sync (sm_100-safe HMMA path).
// R9: attack the remaining L1TEX (55.7% in R8 profile):
//  (a) packed per-node float4 records {x0,x1,x2,theta} built once in init ->
//      feature gather is 2 LDG.128 (quad-deduped) instead of ~8 divergent LDG.32
//  (b) feature STS as 4x STS.128 instead of 16x STS.32 (4x fewer conflicted issues)
// Persistent blocks, bf16 3-term split mma, tanh-silu, register-chained layers.

#define S_SLOTS 4
#define TILE 128
#define NTHREADS 256
#define MAX_NODES (1 << 20)

// ---- smem layout (static, ~37KB) ----
#define XPITCH 48      // 16 bf16 (32B) + 16B pad -> conflict-free ldmatrix
#define WPITCH1 48
#define WPITCH2 144    // 64 bf16 (128B) + 16B pad
#define OFF_XHI  0
#define OFF_XLO  (OFF_XHI + 128 * XPITCH)      // 6144
#define OFF_W1H  (OFF_XLO + 128 * XPITCH)      // 12288
#define OFF_W1L  (OFF_W1H + 64 * WPITCH1)      // 15360
#define OFF_W2H  (OFF_W1L + 64 * WPITCH1)      // 18432
#define OFF_W2L  (OFF_W2H + 64 * WPITCH2)      // 27648
#define OFF_B1   (OFF_W2L + 64 * WPITCH2)      // 36864
#define OFF_B2   (OFF_B1 + 256)
#define OFF_W3   (OFF_B2 + 256)                // 64 float2 pairs
#define OFF_B3   (OFF_W3 + 512)
#define SMEM_BYTES (OFF_B3 + 16)

__device__ int g_edge_is_i64;
__device__ float4 g_node_rec[MAX_NODES];   // {x0, x1, x2, theta}

// init: zero output, detect edge dtype, build packed node records.
// Exactly 2 launches per kernel_launch so ncu -s 5 -c 1 hits the main kernel.
__global__ void init_kernel(float* __restrict__ out, int n,
                            const int* __restrict__ edge32, int n32,
                            const float* __restrict__ x,
                            const float* __restrict__ theta, int nN) {
    int idx = blockIdx.x * blockDim.x + threadIdx.x;
    if (idx < n) out[idx] = 0.0f;
    if (idx < nN) {
        g_node_rec[idx] = make_float4(x[3 * idx + 0], x[3 * idx + 1],
                                      x[3 * idx + 2], theta[idx]);
    }
    if (idx == 0) {
        int any_nonzero = 0;
        for (int s = 0; s < 16; s++) {
            long long pos = 1 + (long long)s * ((n32 - 2) / 16);
            pos |= 1;
            if (pos < n32) any_nonzero |= (edge32[pos] != 0);
        }
        g_edge_is_i64 = any_nonzero ? 0 : 1;
    }
}

// silu via hardware tanh: silu(v) = 0.5v * (1 + tanh(0.5v)). 1 MUFU + 2 FMA.
__device__ __forceinline__ float silu(float v) {
    float h = 0.5f * v;
    float t;
    asm("tanh.approx.f32 %0, %1;" : "=f"(t) : "f"(h));
    return fmaf(h, t, h);
}

__device__ __forceinline__ uint32_t smem_u32(const void* p) {
    uint32_t a;
    asm("{ .reg .u64 t; cvta.to.shared.u64 t, %1; cvt.u32.u64 %0, t; }" : "=r"(a) : "l"(p));
    return a;
}

__device__ __forceinline__ void ldm4(uint32_t addr, uint32_t& r0, uint32_t& r1,
                                     uint32_t& r2, uint32_t& r3) {
    asm volatile("ldmatrix.sync.aligned.m8n8.x4.shared.b16 {%0,%1,%2,%3}, [%4];"
                 : "=r"(r0), "=r"(r1), "=r"(r2), "=r"(r3) : "r"(addr));
}

__device__ __forceinline__ void mma16816(float* c, uint32_t a0, uint32_t a1,
                                         uint32_t a2, uint32_t a3,
                                         uint32_t b0, uint32_t b1) {
    asm volatile(
        "mma.sync.aligned.m16n8k16.row.col.f32.bf16.bf16.f32 "
        "{%0,%1,%2,%3}, {%4,%5,%6,%7}, {%8,%9}, {%0,%1,%2,%3};"
        : "+f"(c[0]), "+f"(c[1]), "+f"(c[2]), "+f"(c[3])
        : "r"(a0), "r"(a1), "r"(a2), "r"(a3), "r"(b0), "r"(b1));
}

__device__ __forceinline__ uint32_t pack_bf2(float v0, float v1) {
    __nv_bfloat162 p = __floats2bfloat162_rn(v0, v1);   // .x = v0 (low half)
    return *reinterpret_cast<uint32_t*>(&p);
}

__global__ __launch_bounds__(NTHREADS, 2)
void gnn_mma_kernel(
    const float* __restrict__ H, const int* __restrict__ edge,
    const float* __restrict__ W1, const float* __restrict__ b1,
    const float* __restrict__ W2, const float* __restrict__ b2,
    const float* __restrict__ W3, const float* __restrict__ b3,
    float* __restrict__ out, int nE, int ntiles)
{
    __shared__ __align__(16) char smem[SMEM_BYTES];
    const uint32_t sb = smem_u32(smem);

    const int t    = threadIdx.x;
    const int lane = t & 31;
    const int w    = t >> 5;           // warp id, rows [16w, 16w+16)
    const int is64 = g_edge_is_i64;
    const long long items = (long long)nE * S_SLOTS;

    // ================= stage weights ONCE per block =================
    for (int idx = t; idx < 64 * 10; idx += NTHREADS) {
        int kk = idx / 64, n = idx % 64;
        float v = W1[kk * 64 + n];
        __nv_bfloat16 hi = __float2bfloat16_rn(v);
        __nv_bfloat16 lo = __float2bfloat16_rn(v - __bfloat162float(hi));
        *(__nv_bfloat16*)(smem + OFF_W1H + n * WPITCH1 + kk * 2) = hi;
        *(__nv_bfloat16*)(smem + OFF_W1L + n * WPITCH1 + kk * 2) = lo;
    }
    if (t < 64) {  // zero pad kk 10..15 of W1
        for (int kk = 10; kk < 16; kk++) {
            *(__nv_bfloat16*)(smem + OFF_W1H + t * WPITCH1 + kk * 2) = __float2bfloat16_rn(0.f);
            *(__nv_bfloat16*)(smem + OFF_W1L + t * WPITCH1 + kk * 2) = __float2bfloat16_rn(0.f);
        }
    }
    for (int idx = t; idx < 64 * 64; idx += NTHREADS) {
        int k = idx >> 6, n = idx & 63;
        float v = W2[k * 64 + n];
        __nv_bfloat16 hi = __float2bfloat16_rn(v);
        __nv_bfloat16 lo = __float2bfloat16_rn(v - __bfloat162float(hi));
        *(__nv_bfloat16*)(smem + OFF_W2H + n * WPITCH2 + k * 2) = hi;
        *(__nv_bfloat16*)(smem + OFF_W2L + n * WPITCH2 + k * 2) = lo;
    }
    if (t < 64) {
        ((float*)(smem + OFF_B1))[t] = b1[t];
        ((float*)(smem + OFF_B2))[t] = b2[t];
        ((float2*)(smem + OFF_W3))[t] = make_float2(W3[2 * t], W3[2 * t + 1]);
    }
    if (t < 2) ((float*)(smem + OFF_B3))[t] = b3[t];

    // ================= ldmatrix address precompute =================
    const int sel = lane >> 3;
    const int r8  = lane & 7;
    const uint32_t a_off  = (uint32_t)((w * 16 + r8 + (sel & 1) * 8) * XPITCH + (sel >> 1) * 16);
    const uint32_t w1_off = (uint32_t)(((sel >> 1) * 8 + r8) * WPITCH1 + (sel & 1) * 16);
    const uint32_t w2_off = (uint32_t)(((sel >> 1) * 8 + r8) * WPITCH2 + (sel & 1) * 16);
    const int cb = 2 * (lane & 3);

    __syncthreads();

    // ================= persistent tile loop =================
    for (int tile = blockIdx.x; tile < ntiles; tile += gridDim.x) {

        // ---- features (t < 128): packed node records, STS.128 writes ----
        if (t < TILE) {
            const long long item = (long long)tile * TILE + t;
            float f[10] = {0, 0, 0, 0, 0, 0, 0, 0, 0, 0};
            if (item < items) {
                const int e = (int)(item >> 2);
                const int s = (int)(item & 3);
                int i_node, j_node;
                if (is64) {
                    const long long* e64 = (const long long*)edge;
                    i_node = (int)e64[e]; j_node = (int)e64[(long long)nE + e];
                } else {
                    i_node = edge[e]; j_node = edge[nE + e];
                }
                const float4 ri = g_node_rec[i_node];
                const float4 rj = g_node_rec[j_node];
                const float dx0 = rj.x - ri.x;
                const float dx1 = rj.y - ri.y;
                const float dx2 = rj.z - ri.z;
                const float rxy2 = dx0 * dx0 + dx1 * dx1;
                float s2, c2; sincosf(2.0f * (rj.w - ri.w), &s2, &c2);
                float sp, cp; sincosf(atan2f(dx1, dx0) - ri.w, &sp, &cp);
                const float sgn = (dx2 > 0.0f) ? 1.0f : ((dx2 < 0.0f) ? -1.0f : 0.0f);
                const float2 hv = *(const float2*)(H + ((long long)j_node * S_SLOTS + s) * 2);
                f[0] = c2 * hv.x - s2 * hv.y;
                f[1] = s2 * hv.x + c2 * hv.y;
                f[2] = sqrtf(rxy2 + dx2 * dx2);
                f[3] = sqrtf(rxy2);
                f[4] = dx2;
                f[5] = sp;  f[6] = cp;  f[7] = s2;  f[8] = c2;  f[9] = sgn * s2;
            }
            // pack hi/lo rows into uint4 and write with STS.128 (4 stores total)
            uint32_t ph[8], pl[8];
            #pragma unroll
            for (int c = 0; c < 10; c += 2) {
                __nv_bfloat16 h0 = __float2bfloat16_rn(f[c]);
                __nv_bfloat16 h1 = __float2bfloat16_rn(f[c + 1]);
                ph[c >> 1] = pack_bf2(__bfloat162float(h0), __bfloat162float(h1));
                pl[c >> 1] = pack_bf2(f[c]     - __bfloat162float(h0),
                                      f[c + 1] - __bfloat162float(h1));
            }
            ph[5] = 0u; ph[6] = 0u; ph[7] = 0u;
            pl[5] = 0u; pl[6] = 0u; pl[7] = 0u;
            uint4* xh = (uint4*)(smem + OFF_XHI + t * XPITCH);
            uint4* xl = (uint4*)(smem + OFF_XLO + t * XPITCH);
            xh[0] = make_uint4(ph[0], ph[1], ph[2], ph[3]);
            xh[1] = make_uint4(ph[4], ph[5], ph[6], ph[7]);
            xl[0] = make_uint4(pl[0], pl[1], pl[2], pl[3]);
            xl[1] = make_uint4(pl[4], pl[5], pl[6], pl[7]);
        }
        __syncthreads();

        // ---- layer 1: X(128x16) @ W1(16x64) ----
        float c1[32];
        #pragma unroll
        for (int i = 0; i < 32; i++) c1[i] = 0.0f;
        {
            uint32_t a1h[4], a1l[4];
            ldm4(sb + OFF_XHI + a_off, a1h[0], a1h[1], a1h[2], a1h[3]);
            ldm4(sb + OFF_XLO + a_off, a1l[0], a1l[1], a1l[2], a1l[3]);
            #pragma unroll
            for (int jp = 0; jp < 8; jp += 2) {
                uint32_t wh0, wh1, wh2, wh3, wl0, wl1, wl2, wl3;
                ldm4(sb + OFF_W1H + jp * 8 * WPITCH1 + w1_off, wh0, wh1, wh2, wh3);
                ldm4(sb + OFF_W1L + jp * 8 * WPITCH1 + w1_off, wl0, wl1, wl2, wl3);
                mma16816(c1 + 4 * jp,     a1h[0], a1h[1], a1h[2], a1h[3], wh0, wh1);
                mma16816(c1 + 4 * jp,     a1l[0], a1l[1], a1l[2], a1l[3], wh0, wh1);
                mma16816(c1 + 4 * jp,     a1h[0], a1h[1], a1h[2], a1h[3], wl0, wl1);
                mma16816(c1 + 4 * jp + 4, a1h[0], a1h[1], a1h[2], a1h[3], wh2, wh3);
                mma16816(c1 + 4 * jp + 4, a1l[0], a1l[1], a1l[2], a1l[3], wh2, wh3);
                mma16816(c1 + 4 * jp + 4, a1h[0], a1h[1], a1h[2], a1h[3], wl2, wl3);
            }
        }

        // ---- layer 2 with fused epilogue-1 (a2 frags live 8 regs only) ----
        float c2acc[32];
        #pragma unroll
        for (int i = 0; i < 32; i++) c2acc[i] = 0.0f;

        #pragma unroll
        for (int q = 0; q < 4; q++) {
            uint32_t a2h[4], a2l[4];
            #pragma unroll
            for (int jj = 0; jj < 2; jj++) {            // n-tiles j = 2q+jj
                const int cjj = 8 * q + 4 * jj;
                const float2 bia = *(const float2*)(smem + OFF_B1 + (8 * (2 * q + jj) + cb) * 4);
                float v0 = silu(c1[cjj + 0] + bia.x);
                float v1 = silu(c1[cjj + 1] + bia.y);
                float v2 = silu(c1[cjj + 2] + bia.x);
                float v3 = silu(c1[cjj + 3] + bia.y);
                __nv_bfloat16 h0 = __float2bfloat16_rn(v0), h1 = __float2bfloat16_rn(v1);
                __nv_bfloat16 h2 = __float2bfloat16_rn(v2), h3 = __float2bfloat16_rn(v3);
                a2h[2 * jj + 0] = pack_bf2(__bfloat162float(h0), __bfloat162float(h1));
                a2h[2 * jj + 1] = pack_bf2(__bfloat162float(h2), __bfloat162float(h3));
                a2l[2 * jj + 0] = pack_bf2(v0 - __bfloat162float(h0), v1 - __bfloat162float(h1));
                a2l[2 * jj + 1] = pack_bf2(v2 - __bfloat162float(h2), v3 - __bfloat162float(h3));
            }
            #pragma unroll
            for (int jp = 0; jp < 8; jp += 2) {
                uint32_t wh0, wh1, wh2, wh3, wl0, wl1, wl2, wl3;
                ldm4(sb + OFF_W2H + jp * 8 * WPITCH2 + q * 32 + w2_off, wh0, wh1, wh2, wh3);
                ldm4(sb + OFF_W2L + jp * 8 * WPITCH2 + q * 32 + w2_off, wl0, wl1, wl2, wl3);
                mma16816(c2acc + 4 * jp,     a2h[0], a2h[1], a2h[2], a2h[3], wh0, wh1);
                mma16816(c2acc + 4 * jp,     a2l[0], a2l[1], a2l[2], a2l[3], wh0, wh1);
                mma16816(c2acc + 4 * jp,     a2h[0], a2h[1], a2h[2], a2h[3], wl0, wl1);
                mma16816(c2acc + 4 * jp + 4, a2h[0], a2h[1], a2h[2], a2h[3], wh2, wh3);
                mma16816(c2acc + 4 * jp + 4, a2l[0], a2l[1], a2l[2], a2l[3], wh2, wh3);
                mma16816(c2acc + 4 * jp + 4, a2h[0], a2h[1], a2h[2], a2h[3], wl2, wl3);
            }
        }

        // ---- epilogue 2: bias + silu + layer3 + quad reduce + scatter ----
        float o0a = 0.f, o1a = 0.f, o0b = 0.f, o1b = 0.f;
        #pragma unroll
        for (int j = 0; j < 8; j++) {
            const int c0 = 8 * j + cb;
            const float2 bia = *(const float2*)(smem + OFF_B2 + c0 * 4);
            const float2 w3a = *(const float2*)(smem + OFF_W3 + c0 * 8);
            const float2 w3b = *(const float2*)(smem + OFF_W3 + (c0 + 1) * 8);
            float v0 = silu(c2acc[4 * j + 0] + bia.x);
            float v1 = silu(c2acc[4 * j + 1] + bia.y);
            float v2 = silu(c2acc[4 * j + 2] + bia.x);
            float v3 = silu(c2acc[4 * j + 3] + bia.y);
            o0a = fmaf(v0, w3a.x, fmaf(v1, w3b.x, o0a));
            o1a = fmaf(v0, w3a.y, fmaf(v1, w3b.y, o1a));
            o0b = fmaf(v2, w3a.x, fmaf(v3, w3b.x, o0b));
            o1b = fmaf(v2, w3a.y, fmaf(v3, w3b.y, o1b));
        }
        #pragma unroll
        for (int m = 1; m <= 2; m <<= 1) {
            o0a += __shfl_xor_sync(0xffffffffu, o0a, m);
            o1a += __shfl_xor_sync(0xffffffffu, o1a, m);
            o0b += __shfl_xor_sync(0xffffffffu, o0b, m);
            o1b += __shfl_xor_sync(0xffffffffu, o1b, m);
        }
        if ((lane & 3) == 0) {
            const float bb0 = ((float*)(smem + OFF_B3))[0];
            const float bb1 = ((float*)(smem + OFF_B3))[1];
            const int g = lane >> 2;
            #pragma unroll
            for (int half = 0; half < 2; half++) {
                const long long item = (long long)tile * TILE + w * 16 + g + 8 * half;
                if (item < items) {
                    const int e = (int)(item >> 2);
                    const int s = (int)(item & 3);
                    int i_node;
                    if (is64) i_node = (int)((const long long*)edge)[e];
                    else      i_node = edge[e];
                    float* o = out + ((long long)i_node * S_SLOTS + s) * 2;
                    atomicAdd(o + 0, (half ? o0b : o0a) + bb0);
                    atomicAdd(o + 1, (half ? o1b : o1a) + bb1);
                }
            }
        }
        __syncthreads();   // protect X tiles before next iteration's writes
    }
}

extern "C" void kernel_launch(void* const* d_in, const int* in_sizes, int n_in,
                              void* d_out, int out_size) {
    const float* x     = (const float*)d_in[0];
    const float* theta = (const float*)d_in[1];
    const float* H     = (const float*)d_in[2];
    const int*   edge  = (const int*)d_in[3];
    const float* W1    = (const float*)d_in[4];
    const float* b1    = (const float*)d_in[5];
    const float* W2    = (const float*)d_in[6];
    const float* b2    = (const float*)d_in[7];
    const float* W3    = (const float*)d_in[8];
    const float* b3    = (const float*)d_in[9];

    const int nE = in_sizes[3] / 2;
    int nN = in_sizes[1];                  // theta has N elements
    if (nN > MAX_NODES) nN = MAX_NODES;

    const int init_n = (out_size > nN) ? out_size : nN;
    init_kernel<<<(init_n + 255) / 256, 256>>>((float*)d_out, out_size,
                                               edge, in_sizes[3], x, theta, nN);

    const long long items = (long long)nE * S_SLOTS;
    const int ntiles = (int)((items + TILE - 1) / TILE);
    int grid = 2 * 148;                    // 2 persistent CTAs per SM
    if (grid > ntiles) grid = ntiles;
    gnn_mma_kernel<<<grid, NTHREADS>>>(H, edge,
                                       W1, b1, W2, b2, W3, b3,
                                       (float*)d_out, nE, ntiles);
}